// round 13
// baseline (speedup 1.0000x reference)
#include <cuda_runtime.h>
#include <math.h>
#include <stdint.h>

#define NPIX 35464
#define NANCH 106392
#define PRE_NMS 6000
#define POOL_K 6656
#define POOLMAX 8192
#define POST_NMS 1000
#define NMS_TH 0.7f
#define CAND_MAX 8192
#define NWORDS 94    // ceil(6000/64)

// ---------------- device scratch ----------------
__device__ float g_f[(size_t)NPIX * 512];     // exact features (pool pixels only)
__device__ float g_fp[(size_t)NPIX * 256];    // fp32 input, pixel-major
__device__ float g_wT[2304 * 512];            // fp32 conv weights [k][oc]
__device__ float g_wd[2304 * 3];              // folded diff weights [k][a]
__device__ float g_wdB[3];                    // folded diff bias
__device__ unsigned g_keys[NANCH];            // approx, then exact for pool anchors
__device__ unsigned g_keysA[NANCH];           // approx keys (filter copy)
__device__ float g_deltas[(size_t)NANCH * 4];
__device__ unsigned g_hist16[65536];
__device__ unsigned g_prefix;
__device__ int g_candCount;
__device__ unsigned long long g_cand[CAND_MAX];
__device__ int g_pixFlag[NPIX];
__device__ int g_poolPix[POOLMAX];
__device__ int g_poolCnt;
__device__ int g_selIdx[PRE_NMS];
__device__ float g_selScore[PRE_NMS];
__device__ float g_boxes[PRE_NMS * 4];
__device__ unsigned long long g_iou[(size_t)PRE_NMS * NWORDS];
__device__ int g_keep[POST_NMS];
__device__ int g_numKeep;

// constants
__constant__ int c_aoff[6] = {0, 79872, 99840, 104832, 106080, 106392};
__constant__ int c_W[5] = {208, 104, 52, 26, 13};
__constant__ int c_H[5] = {128, 64, 32, 16, 8};
__constant__ int c_stride[5] = {4, 8, 16, 32, 64};
__constant__ int c_pixBase[5] = {0, 26624, 33280, 34944, 35360};
__constant__ int c_ws0[15] = {6,4,3, 11,8,6, 23,16,11, 45,32,23, 91,64,45};
__constant__ int c_hs0[15] = {3,4,6, 6,8,12, 12,16,22, 22,32,46, 46,64,90};

// ---------------- prep (all 5 levels fused): NCHW fp32 -> pixel-major fp32 ----------------
__global__ void prep_kernel(const float* __restrict__ p2, const float* __restrict__ p3,
                            const float* __restrict__ p4, const float* __restrict__ p5,
                            const float* __restrict__ p6) {
    __shared__ float sh[32][33];
    int g0 = blockIdx.x * 32;
    int l = 0;
    while (l < 4 && g0 >= c_pixBase[l + 1]) l++;
    const float* f = (l == 0) ? p2 : (l == 1) ? p3 : (l == 2) ? p4 : (l == 3) ? p5 : p6;
    int HW = c_W[l] * c_H[l];
    int base = c_pixBase[l];
    int ic0 = blockIdx.y * 32;
    int tx = threadIdx.x, ty = threadIdx.y;
    int p = g0 - base + tx;
    sh[ty][tx] = (p < HW) ? f[(size_t)(ic0 + ty) * HW + p] : 0.f;
    __syncthreads();
    int pw = g0 - base + ty;
    if (pw < HW)
        g_fp[(size_t)(base + pw) * 256 + ic0 + tx] = sh[tx][ty];
}

// ---------------- weight transpose: [oc][ic][3][3] -> [k][oc], k=tap*256+ic ----------------
__global__ void repackw_kernel(const float* __restrict__ w) {
    int t = blockIdx.x * blockDim.x + threadIdx.x;
    if (t >= 512 * 2304) return;
    int oc = t / 2304, k = t - oc * 2304;
    int tap = k >> 8, ic = k & 255;
    g_wT[k * 512 + oc] = w[oc * 2304 + ic * 9 + tap];
}

// ---------------- fold score-diff head into conv: wd[k][a] = Weff[k][3+a]-Weff[k][a] ----------------
__global__ void fold_kernel(const float* __restrict__ sw, const float* __restrict__ sb,
                            const float* __restrict__ convB) {
    int t = blockIdx.x * blockDim.x + threadIdx.x;
    if (t < 3) {
        float acc = sb[3 + t] - sb[t];
        for (int oc = 0; oc < 512; oc++)
            acc += (sw[(3 + t) * 512 + oc] - sw[t * 512 + oc]) * convB[oc];
        g_wdB[t] = acc;
    }
    if (t >= 2304 * 3) return;
    int k = t / 3, a = t - k * 3;
    const float4* wr = (const float4*)(g_wT + (size_t)k * 512);
    const float4* s0 = (const float4*)(sw + a * 512);
    const float4* s1 = (const float4*)(sw + (3 + a) * 512);
    float acc = 0.f;
#pragma unroll 4
    for (int q = 0; q < 128; q++) {
        float4 wv = wr[q];
        float4 b0 = s0[q], b1 = s1[q];
        acc += wv.x * (b1.x - b0.x) + wv.y * (b1.y - b0.y)
             + wv.z * (b1.z - b0.z) + wv.w * (b1.w - b0.w);
    }
    g_wd[t] = acc;
}

// ---------------- zero everything once ----------------
__global__ void zeroall_kernel() {
    int i = blockIdx.x * blockDim.x + threadIdx.x;
    if (i < 65536) g_hist16[i] = 0;
    if (i < NPIX) g_pixFlag[i] = 0;
    if (i == 0) { g_candCount = 0; g_numKeep = 0; g_poolCnt = 0; }
}

// ---------------- approx scores + fused histogram ----------------
// swizzled smem layout: addr(k) = k*4 + (k>>3)*4 floats -> conflict-free LDS.128
__global__ void __launch_bounds__(256) approx_score_kernel() {
    __shared__ float s_wd[2304 * 4 + 288 * 4];   // 41472 B
    __shared__ float s_bd[3];
    int tid = threadIdx.x;
    for (int k = tid; k < 2304; k += 256) {
        int base = k * 4 + (k >> 3) * 4;
        s_wd[base + 0] = g_wd[k * 3 + 0];
        s_wd[base + 1] = g_wd[k * 3 + 1];
        s_wd[base + 2] = g_wd[k * 3 + 2];
        s_wd[base + 3] = 0.f;
    }
    if (tid < 3) s_bd[tid] = g_wdB[tid];
    __syncthreads();
    int lane = tid & 31;
    const int ic0 = lane * 8;
    for (int p = 0; p < 4; p++) {
        int gw = blockIdx.x * 32 + (tid >> 5) * 4 + p;
        if (gw >= NPIX) break;
        int l = 0;
        while (l < 4 && gw >= c_pixBase[l + 1]) l++;
        const int Wl = c_W[l], Hl = c_H[l];
        int local = gw - c_pixBase[l];
        int py = local / Wl, px = local - py * Wl;
        float d0 = 0.f, d1 = 0.f, d2 = 0.f;
#pragma unroll
        for (int tap = 0; tap < 9; tap++) {
            int dy = tap / 3 - 1, dx = tap % 3 - 1;
            int iy = py + dy, ix = px + dx;
            if ((unsigned)iy >= (unsigned)Hl || (unsigned)ix >= (unsigned)Wl) continue;
            const float* src = g_fp + ((size_t)(c_pixBase[l] + iy * Wl + ix)) * 256 + ic0;
            float4 v0 = *(const float4*)src;
            float4 v1 = *(const float4*)(src + 4);
            float a[8] = {v0.x, v0.y, v0.z, v0.w, v1.x, v1.y, v1.z, v1.w};
            const float* wp = s_wd + tap * 1152 + lane * 36;
#pragma unroll
            for (int j = 0; j < 8; j++) {
                float4 wd = *(const float4*)(wp + j * 4);
                d0 = fmaf(a[j], wd.x, d0);
                d1 = fmaf(a[j], wd.y, d1);
                d2 = fmaf(a[j], wd.z, d2);
            }
        }
#pragma unroll
        for (int off = 16; off; off >>= 1) {
            d0 += __shfl_xor_sync(0xffffffffu, d0, off);
            d1 += __shfl_xor_sync(0xffffffffu, d1, off);
            d2 += __shfl_xor_sync(0xffffffffu, d2, off);
        }
        if (lane < 3) {
            float D = (lane == 0 ? d0 : (lane == 1 ? d1 : d2)) + s_bd[lane];
            float s = 1.f / (1.f + expf(-D));
            unsigned bits = __float_as_uint(s);
            unsigned key = bits ^ ((unsigned)((int)bits >> 31) | 0x80000000u);
            g_keys[gw * 3 + lane] = key;
            g_keysA[gw * 3 + lane] = key;
            atomicAdd(&g_hist16[key >> 16], 1u);
        }
    }
}

// single block, 1024 threads, register-light: two streaming passes over g_hist16
__global__ void __launch_bounds__(1024) select16_kernel(int K) {
    __shared__ unsigned tot[1024];
    int t = threadIdx.x;
    int b0 = t * 64;
    unsigned sum = 0;
    for (int i = 0; i < 64; i++) sum += g_hist16[b0 + i];
    tot[t] = sum;
    __syncthreads();
    for (int d = 1; d < 1024; d <<= 1) {
        unsigned v = (t + d < 1024) ? tot[t + d] : 0u;
        __syncthreads();
        tot[t] += v;
        __syncthreads();
    }
    unsigned suffAfter = (t < 1023) ? tot[t + 1] : 0u;
    if (tot[t] >= (unsigned)K && suffAfter < (unsigned)K) {
        unsigned run = suffAfter;
        for (int i = 63; i >= 0; i--) {
            unsigned before = run;
            run += g_hist16[b0 + i];
            if (run >= (unsigned)K && before < (unsigned)K) {
                g_prefix = ((unsigned)(b0 + i)) << 16;
                break;
            }
        }
    }
}

// ---------------- pool marking ----------------
__global__ void mark_compact_kernel() {
    unsigned T = g_prefix;
    for (int i = blockIdx.x * blockDim.x + threadIdx.x; i < NANCH;
         i += gridDim.x * blockDim.x) {
        if (g_keysA[i] >= T) {
            int pix = i / 3;
            if (atomicExch(&g_pixFlag[pix], 1) == 0) {
                int p = atomicAdd(&g_poolCnt, 1);
                if (p < POOLMAX) g_poolPix[p] = pix;
            }
        }
    }
}

// ---------------- exact fp32 recompute of pool pixels (R1-identical chain) ----------------
// grid (128, 4), 256 threads. Tile: 64 pixels x 128 oc. Thread: 8 px x 4 oc.
// Warp: lanes share the same 8 pixels (smem a-broadcast), consecutive 4-oc slices.
__global__ void __launch_bounds__(256) exact_conv_kernel(const float* __restrict__ bias) {
    __shared__ float sA[64][36];
    __shared__ float sW[32][136];
    __shared__ int s_pix[64], s_base[64], s_W[64], s_H[64], s_py[64], s_px[64];

    const int tid = threadIdx.x;
    const int cnt = g_poolCnt < POOLMAX ? g_poolCnt : POOLMAX;
    const int ptile = blockIdx.x;
    if (ptile * 64 >= cnt) return;
    const int oc0 = blockIdx.y * 128;

    if (tid < 64) {
        int idx = ptile * 64 + tid;
        int pix = (idx < cnt) ? g_poolPix[idx] : -1;
        s_pix[tid] = pix;
        if (pix >= 0) {
            int l = 0;
            while (l < 4 && pix >= c_pixBase[l + 1]) l++;
            int local = pix - c_pixBase[l];
            int Wl = c_W[l];
            s_base[tid] = c_pixBase[l];
            s_W[tid] = Wl;
            s_H[tid] = c_H[l];
            s_py[tid] = local / Wl;
            s_px[tid] = local - (local / Wl) * Wl;
        }
    }
    __syncthreads();

    // compute mapping: warp w handles pixels p0..p0+7 (p0 = w*8); lane handles oc slice
    const int lane = tid & 31, wid = tid >> 5;
    const int p0 = wid * 8;
    const int ocL = lane * 4;

    // loader mapping
    const int ap = tid >> 2;            // 0..63 pixel slot for A loads
    const int akq = (tid & 3) * 8;      // 8-float ic sub-offset
    const int wkk = tid >> 3;           // 0..31 k row for W loads
    const int woc = (tid & 7) * 16;     // 16-float oc group

    float acc[8][4];
#pragma unroll
    for (int i = 0; i < 8; i++)
#pragma unroll
        for (int j = 0; j < 4; j++) acc[i][j] = 0.f;

    for (int chunk = 0; chunk < 72; chunk++) {
        const int tap = chunk >> 3;
        const int ic0 = (chunk & 7) * 32;
        const int dy = tap / 3 - 1;
        const int dx = tap - (tap / 3) * 3 - 1;
        const int k0 = chunk * 32;
        // A: 64 pixels x 32 ic (each thread: 8 floats = 2 float4)
        {
            float4 v0 = make_float4(0.f, 0.f, 0.f, 0.f);
            float4 v1 = v0;
            int pix = s_pix[ap];
            if (pix >= 0) {
                int iy = s_py[ap] + dy, ix = s_px[ap] + dx;
                if ((unsigned)iy < (unsigned)s_H[ap] && (unsigned)ix < (unsigned)s_W[ap]) {
                    int np = s_base[ap] + iy * s_W[ap] + ix;
                    const float* src = g_fp + (size_t)np * 256 + ic0 + akq;
                    v0 = *(const float4*)src;
                    v1 = *(const float4*)(src + 4);
                }
            }
            *(float4*)&sA[ap][akq] = v0;
            *(float4*)&sA[ap][akq + 4] = v1;
        }
        // W: 32 k x 128 oc (each thread: 16 floats = 4 float4)
        {
            const float* src = g_wT + (size_t)(k0 + wkk) * 512 + oc0 + woc;
            float4 w0 = *(const float4*)(src);
            float4 w1 = *(const float4*)(src + 4);
            float4 w2 = *(const float4*)(src + 8);
            float4 w3 = *(const float4*)(src + 12);
            *(float4*)&sW[wkk][woc] = w0;
            *(float4*)&sW[wkk][woc + 4] = w1;
            *(float4*)&sW[wkk][woc + 8] = w2;
            *(float4*)&sW[wkk][woc + 12] = w3;
        }
        __syncthreads();
#pragma unroll 8
        for (int kk = 0; kk < 32; kk++) {
            float4 w = *(const float4*)&sW[kk][ocL];
#pragma unroll
            for (int i = 0; i < 8; i++) {
                float a = sA[p0 + i][kk];
                acc[i][0] = fmaf(a, w.x, acc[i][0]);
                acc[i][1] = fmaf(a, w.y, acc[i][1]);
                acc[i][2] = fmaf(a, w.z, acc[i][2]);
                acc[i][3] = fmaf(a, w.w, acc[i][3]);
            }
        }
        __syncthreads();
    }

    float4 b4 = *(const float4*)(bias + oc0 + ocL);
#pragma unroll
    for (int i = 0; i < 8; i++) {
        int pix = s_pix[p0 + i];
        if (pix >= 0) {
            float4 o;
            o.x = acc[i][0] + b4.x;
            o.y = acc[i][1] + b4.y;
            o.z = acc[i][2] + b4.z;
            o.w = acc[i][3] + b4.w;
            *(float4*)(g_f + (size_t)pix * 512 + oc0 + ocL) = o;
        }
    }
}

// ---------------- exact heads on pool pixels (R1-identical, weights staged in smem) ----------------
__device__ __forceinline__ void heads_pixel(int gw, int lane,
        const float* __restrict__ sw, const float* __restrict__ sb,
        const float* __restrict__ bw, const float* __restrict__ bb)
{
    const float* f = g_f + (size_t)gw * 512;
    float4 v[4];
#pragma unroll
    for (int j = 0; j < 4; j++)
        v[j] = *(const float4*)(f + j * 128 + lane * 4);

    float c[6];
#pragma unroll
    for (int ch = 0; ch < 6; ch++) {
        const float* w = sw + ch * 512;
        float s = 0.f;
#pragma unroll
        for (int j = 0; j < 4; j++) {
            float4 ww = *(const float4*)(w + j * 128 + lane * 4);
            s += v[j].x * ww.x + v[j].y * ww.y + v[j].z * ww.z + v[j].w * ww.w;
        }
#pragma unroll
        for (int off = 16; off; off >>= 1) s += __shfl_xor_sync(0xffffffffu, s, off);
        c[ch] = s + sb[ch];
    }
    float d[12];
#pragma unroll
    for (int ch = 0; ch < 12; ch++) {
        const float* w = bw + ch * 512;
        float s = 0.f;
#pragma unroll
        for (int j = 0; j < 4; j++) {
            float4 ww = *(const float4*)(w + j * 128 + lane * 4);
            s += v[j].x * ww.x + v[j].y * ww.y + v[j].z * ww.z + v[j].w * ww.w;
        }
#pragma unroll
        for (int off = 16; off; off >>= 1) s += __shfl_xor_sync(0xffffffffu, s, off);
        d[ch] = s + bb[ch];
    }
    int base = gw * 3;
    if (lane < 3) {
        float s = 1.f / (1.f + expf(c[lane] - c[3 + lane]));
        unsigned bits = __float_as_uint(s);
        unsigned key = bits ^ ((unsigned)((int)bits >> 31) | 0x80000000u);
        g_keys[base + lane] = key;
    }
    if (lane < 12) {
        g_deltas[(size_t)base * 4 + lane] = d[lane];
    }
}

__global__ void __launch_bounds__(256) heads_pool_kernel(
        const float* __restrict__ sw, const float* __restrict__ sb,
        const float* __restrict__ bw, const float* __restrict__ bb)
{
    __shared__ __align__(16) float s_sw[6 * 512];
    __shared__ __align__(16) float s_bw[12 * 512];
    int tid = threadIdx.x;
    for (int i = tid; i < 6 * 512 / 4; i += 256)
        ((float4*)s_sw)[i] = ((const float4*)sw)[i];
    for (int i = tid; i < 12 * 512 / 4; i += 256)
        ((float4*)s_bw)[i] = ((const float4*)bw)[i];
    __syncthreads();
    int lane = tid & 31, wid = tid >> 5;
    int cnt = g_poolCnt < POOLMAX ? g_poolCnt : POOLMAX;
    for (int i = blockIdx.x * 8 + wid; i < cnt; i += gridDim.x * 8)
        heads_pixel(g_poolPix[i], lane, s_sw, sb, s_bw, bb);
}

// ---------------- compact: filter by approx key, payload exact key ----------------
__global__ void compact_kernel() {
    unsigned T = g_prefix;
    for (int i = blockIdx.x * blockDim.x + threadIdx.x; i < NANCH;
         i += gridDim.x * blockDim.x) {
        if (g_keysA[i] >= T) {
            unsigned k = g_keys[i];   // exact (pixel is in pool by construction)
            int p = atomicAdd(&g_candCount, 1);
            if (p < CAND_MAX)
                g_cand[p] = ((unsigned long long)k << 32) | (unsigned)(~i);
        }
    }
}

// ---------------- bitonic sort of candidates (key desc, idx asc) ----------------
__global__ void sort_kernel() {
    extern __shared__ unsigned long long s[];
    int tid = threadIdx.x;
    int cnt = g_candCount;
    if (cnt > CAND_MAX) cnt = CAND_MAX;
    for (int i = tid; i < CAND_MAX; i += blockDim.x)
        s[i] = (i < cnt) ? g_cand[i] : 0ULL;
    __syncthreads();
    for (int k = 2; k <= CAND_MAX; k <<= 1) {
        for (int j = k >> 1; j > 0; j >>= 1) {
            for (int i = tid; i < CAND_MAX; i += blockDim.x) {
                int ixj = i ^ j;
                if (ixj > i) {
                    unsigned long long a = s[i], b = s[ixj];
                    bool desc = ((i & k) == 0);
                    if (desc ? (a < b) : (a > b)) { s[i] = b; s[ixj] = a; }
                }
            }
            __syncthreads();
        }
    }
    for (int i = tid; i < PRE_NMS; i += blockDim.x) {
        unsigned long long e = s[i];
        unsigned idx = ~(unsigned)(e & 0xffffffffu);
        unsigned key = (unsigned)(e >> 32);
        unsigned bits = (key & 0x80000000u) ? (key ^ 0x80000000u) : ~key;
        g_selIdx[i] = (int)idx;
        g_selScore[i] = __uint_as_float(bits);
    }
}

// ---------------- decode + clip only selected 6000 ----------------
__global__ void decode_kernel(const float* __restrict__ im_info) {
    int i = blockIdx.x * blockDim.x + threadIdx.x;
    if (i >= PRE_NMS) return;
    int idx = g_selIdx[i];
    int l = 0;
    while (l < 4 && idx >= c_aoff[l + 1]) l++;
    int local = idx - c_aoff[l];
    int p = local / 3, a = local - p * 3;
    int W = c_W[l];
    int y = p / W, x = p - y * W;
    float stride = (float)c_stride[l];
    float cb = (stride - 1.f) * 0.5f;
    float ws = c_ws0[l * 3 + a] * 8.f, hs = c_hs0[l * 3 + a] * 8.f;
    float sx = x * stride, sy = y * stride;
    float ax1 = sx + cb - 0.5f * (ws - 1.f);
    float ay1 = sy + cb - 0.5f * (hs - 1.f);
    float ax2 = sx + cb + 0.5f * (ws - 1.f);
    float ay2 = sy + cb + 0.5f * (hs - 1.f);
    float w = ax2 - ax1 + 1.f, h = ay2 - ay1 + 1.f;
    float cx = ax1 + 0.5f * w, cy = ay1 + 0.5f * h;
    const float* dd = g_deltas + (size_t)idx * 4;
    float pcx = dd[0] * w + cx;
    float pcy = dd[1] * h + cy;
    float pw = expf(dd[2]) * w;
    float ph = expf(dd[3]) * h;
    float imW = im_info[1] - 1.f, imH = im_info[0] - 1.f;
    g_boxes[i * 4 + 0] = fminf(fmaxf(pcx - 0.5f * pw, 0.f), imW);
    g_boxes[i * 4 + 1] = fminf(fmaxf(pcy - 0.5f * ph, 0.f), imH);
    g_boxes[i * 4 + 2] = fminf(fmaxf(pcx + 0.5f * pw, 0.f), imW);
    g_boxes[i * 4 + 3] = fminf(fmaxf(pcy + 0.5f * ph, 0.f), imH);
}

// ---------------- IoU suppression bitmask (smem-tiled) ----------------
__global__ void iou_kernel() {
    __shared__ float4 sj[64];
    int wb = blockIdx.y;
    int t = threadIdx.x;
    int j0 = wb * 64;
    {
        int j = j0 + t;
        sj[t] = (j < PRE_NMS) ? ((const float4*)g_boxes)[j]
                              : make_float4(0.f, 0.f, 0.f, 0.f);
    }
    __syncthreads();
    int i = blockIdx.x * 64 + t;
    if (i >= PRE_NMS) return;
    float4 bi = ((const float4*)g_boxes)[i];
    float areaI = (bi.z - bi.x + 1.f) * (bi.w - bi.y + 1.f);
    unsigned long long m = 0;
    int jend = PRE_NMS - j0; if (jend > 64) jend = 64;
    for (int jj = 0; jj < jend; jj++) {
        float4 bj = sj[jj];
        float areaJ = (bj.z - bj.x + 1.f) * (bj.w - bj.y + 1.f);
        float iw = fminf(bi.z, bj.z) - fmaxf(bi.x, bj.x) + 1.f;
        float ih = fminf(bi.w, bj.w) - fmaxf(bi.y, bj.y) + 1.f;
        iw = fmaxf(iw, 0.f); ih = fmaxf(ih, 0.f);
        float inter = iw * ih;
        float iou = inter / (areaJ + areaI - inter);
        if (iou > NMS_TH) m |= (1ULL << jj);
    }
    g_iou[(size_t)i * NWORDS + wb] = m;
}

// ---------------- single-warp greedy NMS with 8-way row prefetch ----------------
__global__ void nms_kernel() {
    int lane = threadIdx.x;
    unsigned long long rem0 = 0, rem1 = 0, rem2 = 0;
    int w2 = lane + 64;
    if (w2 == 93) rem2 = ~((1ULL << 48) - 1ULL);
    else if (w2 > 93) rem2 = ~0ULL;
    int nk = 0;
    while (nk < POST_NMS) {
        unsigned long long a0 = ~rem0, a1 = ~rem1, a2 = ~rem2;
        int cand[8];
#pragma unroll
        for (int t = 0; t < 8; t++) cand[t] = -1;
#pragma unroll
        for (int t = 0; t < 8; t++) {
            unsigned b0 = __ballot_sync(0xffffffffu, a0 != 0ULL);
            unsigned b1 = __ballot_sync(0xffffffffu, a1 != 0ULL);
            unsigned b2 = __ballot_sync(0xffffffffu, a2 != 0ULL);
            int slot = -1, src = 0;
            if (b0) { slot = 0; src = __ffs(b0) - 1; }
            else if (b1) { slot = 1; src = __ffs(b1) - 1; }
            else if (b2) { slot = 2; src = __ffs(b2) - 1; }
            if (slot < 0) break;
            unsigned long long mysel = (slot == 0) ? a0 : ((slot == 1) ? a1 : a2);
            int mybit = __ffsll((long long)mysel) - 1;
            int bit = __shfl_sync(0xffffffffu, mybit, src);
            cand[t] = (slot * 32 + src) * 64 + bit;
            if (lane == src) {
                if (slot == 0) a0 &= (a0 - 1);
                else if (slot == 1) a1 &= (a1 - 1);
                else a2 &= (a2 - 1);
            }
        }
        if (cand[0] < 0) break;
        unsigned long long r[8][3];
#pragma unroll
        for (int t = 0; t < 8; t++) {
            if (cand[t] >= 0) {
                const unsigned long long* row = g_iou + (size_t)cand[t] * NWORDS;
                r[t][0] = __ldg(row + lane);
                r[t][1] = __ldg(row + lane + 32);
                r[t][2] = (w2 < NWORDS) ? __ldg(row + w2) : 0ULL;
            } else {
                r[t][0] = r[t][1] = r[t][2] = 0ULL;
            }
        }
#pragma unroll
        for (int t = 0; t < 8; t++) {
            int idx = cand[t];
            if (idx < 0 || nk >= POST_NMS) break;
            if (t > 0) {
                int w = idx >> 6, b = idx & 63;
                unsigned long long mine = (w < 32) ? rem0 : ((w < 64) ? rem1 : rem2);
                unsigned long long ow = __shfl_sync(0xffffffffu, mine, w & 31);
                if ((ow >> b) & 1ULL) continue;
            }
            if (lane == 0) g_keep[nk] = idx;
            nk++;
            rem0 |= r[t][0]; rem1 |= r[t][1]; rem2 |= r[t][2];
        }
    }
    if (lane == 0) g_numKeep = nk;
}

// ---------------- assemble output (1000 x 6) ----------------
__global__ void output_kernel(float* __restrict__ out) {
    int i = blockIdx.x * blockDim.x + threadIdx.x;
    if (i >= POST_NMS) return;
    float x1 = 0, y1 = 0, x2 = 0, y2 = 0, s = 0;
    int nk = g_numKeep;
    if (i < nk) {
        int k = g_keep[i];
        x1 = g_boxes[k * 4 + 0]; y1 = g_boxes[k * 4 + 1];
        x2 = g_boxes[k * 4 + 2]; y2 = g_boxes[k * 4 + 3];
        s = g_selScore[k];
    }
    out[i * 6 + 0] = 0.f;
    out[i * 6 + 1] = x1;
    out[i * 6 + 2] = y1;
    out[i * 6 + 3] = x2;
    out[i * 6 + 4] = y2;
    out[i * 6 + 5] = s;
}

// ---------------- launch ----------------
extern "C" void kernel_launch(void* const* d_in, const int* in_sizes, int n_in,
                              void* d_out, int out_size) {
    const float* feats[5];
    for (int i = 0; i < 5; i++) feats[i] = (const float*)d_in[i];
    const float* im_info = (const float*)d_in[5];
    const float* convW = (const float*)d_in[6];
    const float* convB = (const float*)d_in[7];
    const float* sw = (const float*)d_in[8];
    const float* sb = (const float*)d_in[9];
    const float* bw = (const float*)d_in[10];
    const float* bb = (const float*)d_in[11];
    float* out = (float*)d_out;

    static bool attrDone = false;
    if (!attrDone) {
        cudaFuncSetAttribute(sort_kernel,
                             cudaFuncAttributeMaxDynamicSharedMemorySize, CAND_MAX * 8);
        attrDone = true;
    }

    prep_kernel<<<dim3(1109, 8), dim3(32, 32)>>>(feats[0], feats[1], feats[2],
                                                 feats[3], feats[4]);
    repackw_kernel<<<(512 * 2304 + 255) / 256, 256>>>(convW);
    fold_kernel<<<(2304 * 3 + 255) / 256, 256>>>(sw, sb, convB);
    zeroall_kernel<<<(65536 + 255) / 256, 256>>>();
    approx_score_kernel<<<1109, 256>>>();
    select16_kernel<<<1, 1024>>>(POOL_K);
    mark_compact_kernel<<<416, 256>>>();
    exact_conv_kernel<<<dim3(128, 4), 256>>>(convB);
    heads_pool_kernel<<<128, 256>>>(sw, sb, bw, bb);
    compact_kernel<<<416, 256>>>();
    sort_kernel<<<1, 1024, CAND_MAX * 8>>>();
    decode_kernel<<<(PRE_NMS + 255) / 256, 256>>>(im_info);
    iou_kernel<<<dim3(94, 94), 64>>>();
    nms_kernel<<<1, 32>>>();
    output_kernel<<<(POST_NMS + 255) / 256, 256>>>(out);
}

// round 14
// speedup vs baseline: 1.1243x; 1.1243x over previous
#include <cuda_runtime.h>
#include <math.h>
#include <stdint.h>

#define NPIX 35464
#define NANCH 106392
#define PRE_NMS 6000
#define POOL_K 6656
#define POOLMAX 8192
#define POST_NMS 1000
#define NMS_TH 0.7f
#define CAND_MAX 8192
#define NWORDS 94    // ceil(6000/64)

// ---------------- device scratch ----------------
__device__ float g_f[(size_t)NPIX * 512];     // exact features (pool pixels only)
__device__ float g_fp[(size_t)NPIX * 256];    // fp32 input, pixel-major
__device__ float g_wT[2304 * 512];            // fp32 conv weights [k][oc]
__device__ float g_wd[2304 * 3];              // folded diff weights [k][a]
__device__ float g_wdB[3];                    // folded diff bias
__device__ unsigned g_keys[NANCH];            // approx, then exact for pool anchors
__device__ unsigned g_keysA[NANCH];           // approx keys (filter copy)
__device__ float g_deltas[(size_t)NANCH * 4];
__device__ unsigned g_hist16[65536];
__device__ unsigned g_prefix;
__device__ int g_candCount;
__device__ unsigned long long g_cand[CAND_MAX];
__device__ int g_pixFlag[NPIX];
__device__ int g_poolPix[POOLMAX];
__device__ int g_poolCnt;
__device__ int g_selIdx[PRE_NMS];
__device__ float g_selScore[PRE_NMS];
__device__ float g_boxes[PRE_NMS * 4];
__device__ unsigned long long g_iou[(size_t)PRE_NMS * NWORDS];
__device__ int g_keep[POST_NMS];
__device__ int g_numKeep;

// constants
__constant__ int c_aoff[6] = {0, 79872, 99840, 104832, 106080, 106392};
__constant__ int c_W[5] = {208, 104, 52, 26, 13};
__constant__ int c_H[5] = {128, 64, 32, 16, 8};
__constant__ int c_stride[5] = {4, 8, 16, 32, 64};
__constant__ int c_pixBase[5] = {0, 26624, 33280, 34944, 35360};
__constant__ int c_ws0[15] = {6,4,3, 11,8,6, 23,16,11, 45,32,23, 91,64,45};
__constant__ int c_hs0[15] = {3,4,6, 6,8,12, 12,16,22, 22,32,46, 46,64,90};

// ---------------- prep (all 5 levels fused): NCHW fp32 -> pixel-major fp32 ----------------
__global__ void prep_kernel(const float* __restrict__ p2, const float* __restrict__ p3,
                            const float* __restrict__ p4, const float* __restrict__ p5,
                            const float* __restrict__ p6) {
    __shared__ float sh[32][33];
    int g0 = blockIdx.x * 32;
    int l = 0;
    while (l < 4 && g0 >= c_pixBase[l + 1]) l++;
    const float* f = (l == 0) ? p2 : (l == 1) ? p3 : (l == 2) ? p4 : (l == 3) ? p5 : p6;
    int HW = c_W[l] * c_H[l];
    int base = c_pixBase[l];
    int ic0 = blockIdx.y * 32;
    int tx = threadIdx.x, ty = threadIdx.y;
    int p = g0 - base + tx;
    sh[ty][tx] = (p < HW) ? f[(size_t)(ic0 + ty) * HW + p] : 0.f;
    __syncthreads();
    int pw = g0 - base + ty;
    if (pw < HW)
        g_fp[(size_t)(base + pw) * 256 + ic0 + tx] = sh[tx][ty];
}

// ---------------- weight transpose + zero scratch ----------------
__global__ void repackw_kernel(const float* __restrict__ w) {
    int t = blockIdx.x * blockDim.x + threadIdx.x;
    if (t < 65536) g_hist16[t] = 0;
    if (t < NPIX) g_pixFlag[t] = 0;
    if (t == 0) { g_candCount = 0; g_numKeep = 0; g_poolCnt = 0; }
    if (t >= 512 * 2304) return;
    int oc = t / 2304, k = t - oc * 2304;
    int tap = k >> 8, ic = k & 255;
    g_wT[k * 512 + oc] = w[oc * 2304 + ic * 9 + tap];
}

// ---------------- fold score-diff head into conv: wd[k][a] = Weff[k][3+a]-Weff[k][a] ----------------
__global__ void fold_kernel(const float* __restrict__ sw, const float* __restrict__ sb,
                            const float* __restrict__ convB) {
    int t = blockIdx.x * blockDim.x + threadIdx.x;
    if (t < 3) {
        float acc = sb[3 + t] - sb[t];
        for (int oc = 0; oc < 512; oc++)
            acc += (sw[(3 + t) * 512 + oc] - sw[t * 512 + oc]) * convB[oc];
        g_wdB[t] = acc;
    }
    if (t >= 2304 * 3) return;
    int k = t / 3, a = t - k * 3;
    const float4* wr = (const float4*)(g_wT + (size_t)k * 512);
    const float4* s0 = (const float4*)(sw + a * 512);
    const float4* s1 = (const float4*)(sw + (3 + a) * 512);
    float acc = 0.f;
#pragma unroll 4
    for (int q = 0; q < 128; q++) {
        float4 wv = wr[q];
        float4 b0 = s0[q], b1 = s1[q];
        acc += wv.x * (b1.x - b0.x) + wv.y * (b1.y - b0.y)
             + wv.z * (b1.z - b0.z) + wv.w * (b1.w - b0.w);
    }
    g_wd[t] = acc;
}

// ---------------- approx scores + fused histogram ----------------
// swizzled smem layout: addr(k) = k*4 + (k>>3)*4 floats -> conflict-free LDS.128
__global__ void __launch_bounds__(256) approx_score_kernel() {
    __shared__ float s_wd[2304 * 4 + 288 * 4];   // 41472 B
    __shared__ float s_bd[3];
    int tid = threadIdx.x;
    for (int k = tid; k < 2304; k += 256) {
        int base = k * 4 + (k >> 3) * 4;
        s_wd[base + 0] = g_wd[k * 3 + 0];
        s_wd[base + 1] = g_wd[k * 3 + 1];
        s_wd[base + 2] = g_wd[k * 3 + 2];
        s_wd[base + 3] = 0.f;
    }
    if (tid < 3) s_bd[tid] = g_wdB[tid];
    __syncthreads();
    int lane = tid & 31;
    const int ic0 = lane * 8;
    for (int p = 0; p < 4; p++) {
        int gw = blockIdx.x * 32 + (tid >> 5) * 4 + p;
        if (gw >= NPIX) break;
        int l = 0;
        while (l < 4 && gw >= c_pixBase[l + 1]) l++;
        const int Wl = c_W[l], Hl = c_H[l];
        int local = gw - c_pixBase[l];
        int py = local / Wl, px = local - py * Wl;
        float d0 = 0.f, d1 = 0.f, d2 = 0.f;
#pragma unroll
        for (int tap = 0; tap < 9; tap++) {
            int dy = tap / 3 - 1, dx = tap % 3 - 1;
            int iy = py + dy, ix = px + dx;
            if ((unsigned)iy >= (unsigned)Hl || (unsigned)ix >= (unsigned)Wl) continue;
            const float* src = g_fp + ((size_t)(c_pixBase[l] + iy * Wl + ix)) * 256 + ic0;
            float4 v0 = *(const float4*)src;
            float4 v1 = *(const float4*)(src + 4);
            float a[8] = {v0.x, v0.y, v0.z, v0.w, v1.x, v1.y, v1.z, v1.w};
            const float* wp = s_wd + tap * 1152 + lane * 36;
#pragma unroll
            for (int j = 0; j < 8; j++) {
                float4 wd = *(const float4*)(wp + j * 4);
                d0 = fmaf(a[j], wd.x, d0);
                d1 = fmaf(a[j], wd.y, d1);
                d2 = fmaf(a[j], wd.z, d2);
            }
        }
#pragma unroll
        for (int off = 16; off; off >>= 1) {
            d0 += __shfl_xor_sync(0xffffffffu, d0, off);
            d1 += __shfl_xor_sync(0xffffffffu, d1, off);
            d2 += __shfl_xor_sync(0xffffffffu, d2, off);
        }
        if (lane < 3) {
            float D = (lane == 0 ? d0 : (lane == 1 ? d1 : d2)) + s_bd[lane];
            float s = 1.f / (1.f + expf(-D));
            unsigned bits = __float_as_uint(s);
            unsigned key = bits ^ ((unsigned)((int)bits >> 31) | 0x80000000u);
            g_keys[gw * 3 + lane] = key;
            g_keysA[gw * 3 + lane] = key;
            atomicAdd(&g_hist16[key >> 16], 1u);
        }
    }
}

// single block, 1024 threads, register-light: two streaming passes over g_hist16
__global__ void __launch_bounds__(1024) select16_kernel(int K) {
    __shared__ unsigned tot[1024];
    int t = threadIdx.x;
    int b0 = t * 64;
    unsigned sum = 0;
    for (int i = 0; i < 64; i++) sum += g_hist16[b0 + i];
    tot[t] = sum;
    __syncthreads();
    for (int d = 1; d < 1024; d <<= 1) {
        unsigned v = (t + d < 1024) ? tot[t + d] : 0u;
        __syncthreads();
        tot[t] += v;
        __syncthreads();
    }
    unsigned suffAfter = (t < 1023) ? tot[t + 1] : 0u;
    if (tot[t] >= (unsigned)K && suffAfter < (unsigned)K) {
        unsigned run = suffAfter;
        for (int i = 63; i >= 0; i--) {
            unsigned before = run;
            run += g_hist16[b0 + i];
            if (run >= (unsigned)K && before < (unsigned)K) {
                g_prefix = ((unsigned)(b0 + i)) << 16;
                break;
            }
        }
    }
}

// ---------------- pool marking ----------------
__global__ void mark_compact_kernel() {
    unsigned T = g_prefix;
    for (int i = blockIdx.x * blockDim.x + threadIdx.x; i < NANCH;
         i += gridDim.x * blockDim.x) {
        if (g_keysA[i] >= T) {
            int pix = i / 3;
            if (atomicExch(&g_pixFlag[pix], 1) == 0) {
                int p = atomicAdd(&g_poolCnt, 1);
                if (p < POOLMAX) g_poolPix[p] = pix;
            }
        }
    }
}

// ---------------- exact fp32 recompute of pool pixels (R1-identical chain) ----------------
// grid (256, 2), 256 threads. Tile: 32 pixels x 256 oc. Thread: 4 px x 8 oc.
__global__ void __launch_bounds__(256) exact_conv_kernel(const float* __restrict__ bias) {
    __shared__ float sA[32][33];
    __shared__ float sW[32][264];
    __shared__ int s_pix[32], s_base[32], s_W[32], s_H[32], s_py[32], s_px[32];

    const int tid = threadIdx.x;
    const int cnt = g_poolCnt < POOLMAX ? g_poolCnt : POOLMAX;
    const int ptile = blockIdx.x;
    if (ptile * 32 >= cnt) return;
    const int oc0 = blockIdx.y * 256;

    if (tid < 32) {
        int idx = ptile * 32 + tid;
        int pix = (idx < cnt) ? g_poolPix[idx] : -1;
        s_pix[tid] = pix;
        if (pix >= 0) {
            int l = 0;
            while (l < 4 && pix >= c_pixBase[l + 1]) l++;
            int local = pix - c_pixBase[l];
            int Wl = c_W[l];
            s_base[tid] = c_pixBase[l];
            s_W[tid] = Wl;
            s_H[tid] = c_H[l];
            s_py[tid] = local / Wl;
            s_px[tid] = local - (local / Wl) * Wl;
        }
    }
    __syncthreads();

    const int lane = tid & 31, wid = tid >> 5;
    const int ocL = wid * 32 + (lane >> 3) * 8;
    const int p0 = (lane & 7) * 4;

    const int ap = tid >> 3;
    const int akq = (tid & 7) * 4;
    const int wkk = tid >> 6;
    const int woc = (tid & 63) * 4;

    float acc[4][8];
#pragma unroll
    for (int i = 0; i < 4; i++)
#pragma unroll
        for (int j = 0; j < 8; j++) acc[i][j] = 0.f;

    for (int chunk = 0; chunk < 72; chunk++) {
        const int tap = chunk >> 3;
        const int ic0 = (chunk & 7) * 32;
        const int dy = tap / 3 - 1;
        const int dx = tap - (tap / 3) * 3 - 1;
        const int k0 = chunk * 32;
        {
            float4 val = make_float4(0.f, 0.f, 0.f, 0.f);
            int pix = s_pix[ap];
            if (pix >= 0) {
                int iy = s_py[ap] + dy, ix = s_px[ap] + dx;
                if ((unsigned)iy < (unsigned)s_H[ap] && (unsigned)ix < (unsigned)s_W[ap]) {
                    int np = s_base[ap] + iy * s_W[ap] + ix;
                    val = *(const float4*)(g_fp + (size_t)np * 256 + ic0 + akq);
                }
            }
            sA[ap][akq + 0] = val.x;
            sA[ap][akq + 1] = val.y;
            sA[ap][akq + 2] = val.z;
            sA[ap][akq + 3] = val.w;
        }
#pragma unroll
        for (int r = 0; r < 8; r++) {
            int kk = r * 4 + wkk;
            *(float4*)&sW[kk][woc] =
                *(const float4*)(g_wT + (size_t)(k0 + kk) * 512 + oc0 + woc);
        }
        __syncthreads();
#pragma unroll 8
        for (int kk = 0; kk < 32; kk++) {
            float a0 = sA[p0 + 0][kk];
            float a1 = sA[p0 + 1][kk];
            float a2 = sA[p0 + 2][kk];
            float a3 = sA[p0 + 3][kk];
#pragma unroll
            for (int j = 0; j < 8; j++) {
                float w = sW[kk][ocL + j];
                acc[0][j] = fmaf(a0, w, acc[0][j]);
                acc[1][j] = fmaf(a1, w, acc[1][j]);
                acc[2][j] = fmaf(a2, w, acc[2][j]);
                acc[3][j] = fmaf(a3, w, acc[3][j]);
            }
        }
        __syncthreads();
    }

#pragma unroll
    for (int i = 0; i < 4; i++) {
        int pix = s_pix[p0 + i];
        if (pix >= 0) {
            float* o = g_f + (size_t)pix * 512 + oc0 + ocL;
#pragma unroll
            for (int j = 0; j < 8; j++) o[j] = acc[i][j] + bias[oc0 + ocL + j];
        }
    }
}

// ---------------- exact heads on pool pixels (R1-identical, weights staged in smem) ----------------
__device__ __forceinline__ void heads_pixel(int gw, int lane,
        const float* __restrict__ sw, const float* __restrict__ sb,
        const float* __restrict__ bw, const float* __restrict__ bb)
{
    const float* f = g_f + (size_t)gw * 512;
    float4 v[4];
#pragma unroll
    for (int j = 0; j < 4; j++)
        v[j] = *(const float4*)(f + j * 128 + lane * 4);

    float c[6];
#pragma unroll
    for (int ch = 0; ch < 6; ch++) {
        const float* w = sw + ch * 512;
        float s = 0.f;
#pragma unroll
        for (int j = 0; j < 4; j++) {
            float4 ww = *(const float4*)(w + j * 128 + lane * 4);
            s += v[j].x * ww.x + v[j].y * ww.y + v[j].z * ww.z + v[j].w * ww.w;
        }
#pragma unroll
        for (int off = 16; off; off >>= 1) s += __shfl_xor_sync(0xffffffffu, s, off);
        c[ch] = s + sb[ch];
    }
    float d[12];
#pragma unroll
    for (int ch = 0; ch < 12; ch++) {
        const float* w = bw + ch * 512;
        float s = 0.f;
#pragma unroll
        for (int j = 0; j < 4; j++) {
            float4 ww = *(const float4*)(w + j * 128 + lane * 4);
            s += v[j].x * ww.x + v[j].y * ww.y + v[j].z * ww.z + v[j].w * ww.w;
        }
#pragma unroll
        for (int off = 16; off; off >>= 1) s += __shfl_xor_sync(0xffffffffu, s, off);
        d[ch] = s + bb[ch];
    }
    int base = gw * 3;
    if (lane < 3) {
        float s = 1.f / (1.f + expf(c[lane] - c[3 + lane]));
        unsigned bits = __float_as_uint(s);
        unsigned key = bits ^ ((unsigned)((int)bits >> 31) | 0x80000000u);
        g_keys[base + lane] = key;
    }
    if (lane < 12) {
        g_deltas[(size_t)base * 4 + lane] = d[lane];
    }
}

__global__ void __launch_bounds__(256) heads_pool_kernel(
        const float* __restrict__ sw, const float* __restrict__ sb,
        const float* __restrict__ bw, const float* __restrict__ bb)
{
    __shared__ __align__(16) float s_sw[6 * 512];
    __shared__ __align__(16) float s_bw[12 * 512];
    int tid = threadIdx.x;
    for (int i = tid; i < 6 * 512 / 4; i += 256)
        ((float4*)s_sw)[i] = ((const float4*)sw)[i];
    for (int i = tid; i < 12 * 512 / 4; i += 256)
        ((float4*)s_bw)[i] = ((const float4*)bw)[i];
    __syncthreads();
    int lane = tid & 31, wid = tid >> 5;
    int cnt = g_poolCnt < POOLMAX ? g_poolCnt : POOLMAX;
    for (int i = blockIdx.x * 8 + wid; i < cnt; i += gridDim.x * 8)
        heads_pixel(g_poolPix[i], lane, s_sw, sb, s_bw, bb);
}

// ---------------- compact: filter by approx key, payload exact key ----------------
__global__ void compact_kernel() {
    unsigned T = g_prefix;
    for (int i = blockIdx.x * blockDim.x + threadIdx.x; i < NANCH;
         i += gridDim.x * blockDim.x) {
        if (g_keysA[i] >= T) {
            unsigned k = g_keys[i];   // exact (pixel is in pool by construction)
            int p = atomicAdd(&g_candCount, 1);
            if (p < CAND_MAX)
                g_cand[p] = ((unsigned long long)k << 32) | (unsigned)(~i);
        }
    }
}

// ---------------- bitonic sort of candidates (key desc, idx asc) ----------------
__global__ void sort_kernel() {
    extern __shared__ unsigned long long s[];
    int tid = threadIdx.x;
    int cnt = g_candCount;
    if (cnt > CAND_MAX) cnt = CAND_MAX;
    for (int i = tid; i < CAND_MAX; i += blockDim.x)
        s[i] = (i < cnt) ? g_cand[i] : 0ULL;
    __syncthreads();
    for (int k = 2; k <= CAND_MAX; k <<= 1) {
        for (int j = k >> 1; j > 0; j >>= 1) {
            for (int i = tid; i < CAND_MAX; i += blockDim.x) {
                int ixj = i ^ j;
                if (ixj > i) {
                    unsigned long long a = s[i], b = s[ixj];
                    bool desc = ((i & k) == 0);
                    if (desc ? (a < b) : (a > b)) { s[i] = b; s[ixj] = a; }
                }
            }
            __syncthreads();
        }
    }
    for (int i = tid; i < PRE_NMS; i += blockDim.x) {
        unsigned long long e = s[i];
        unsigned idx = ~(unsigned)(e & 0xffffffffu);
        unsigned key = (unsigned)(e >> 32);
        unsigned bits = (key & 0x80000000u) ? (key ^ 0x80000000u) : ~key;
        g_selIdx[i] = (int)idx;
        g_selScore[i] = __uint_as_float(bits);
    }
}

// ---------------- decode + clip only selected 6000 ----------------
__global__ void decode_kernel(const float* __restrict__ im_info) {
    int i = blockIdx.x * blockDim.x + threadIdx.x;
    if (i >= PRE_NMS) return;
    int idx = g_selIdx[i];
    int l = 0;
    while (l < 4 && idx >= c_aoff[l + 1]) l++;
    int local = idx - c_aoff[l];
    int p = local / 3, a = local - p * 3;
    int W = c_W[l];
    int y = p / W, x = p - y * W;
    float stride = (float)c_stride[l];
    float cb = (stride - 1.f) * 0.5f;
    float ws = c_ws0[l * 3 + a] * 8.f, hs = c_hs0[l * 3 + a] * 8.f;
    float sx = x * stride, sy = y * stride;
    float ax1 = sx + cb - 0.5f * (ws - 1.f);
    float ay1 = sy + cb - 0.5f * (hs - 1.f);
    float ax2 = sx + cb + 0.5f * (ws - 1.f);
    float ay2 = sy + cb + 0.5f * (hs - 1.f);
    float w = ax2 - ax1 + 1.f, h = ay2 - ay1 + 1.f;
    float cx = ax1 + 0.5f * w, cy = ay1 + 0.5f * h;
    const float* dd = g_deltas + (size_t)idx * 4;
    float pcx = dd[0] * w + cx;
    float pcy = dd[1] * h + cy;
    float pw = expf(dd[2]) * w;
    float ph = expf(dd[3]) * h;
    float imW = im_info[1] - 1.f, imH = im_info[0] - 1.f;
    g_boxes[i * 4 + 0] = fminf(fmaxf(pcx - 0.5f * pw, 0.f), imW);
    g_boxes[i * 4 + 1] = fminf(fmaxf(pcy - 0.5f * ph, 0.f), imH);
    g_boxes[i * 4 + 2] = fminf(fmaxf(pcx + 0.5f * pw, 0.f), imW);
    g_boxes[i * 4 + 3] = fminf(fmaxf(pcy + 0.5f * ph, 0.f), imH);
}

// ---------------- IoU suppression bitmask (smem-tiled) ----------------
__global__ void iou_kernel() {
    __shared__ float4 sj[64];
    int wb = blockIdx.y;
    int t = threadIdx.x;
    int j0 = wb * 64;
    {
        int j = j0 + t;
        sj[t] = (j < PRE_NMS) ? ((const float4*)g_boxes)[j]
                              : make_float4(0.f, 0.f, 0.f, 0.f);
    }
    __syncthreads();
    int i = blockIdx.x * 64 + t;
    if (i >= PRE_NMS) return;
    float4 bi = ((const float4*)g_boxes)[i];
    float areaI = (bi.z - bi.x + 1.f) * (bi.w - bi.y + 1.f);
    unsigned long long m = 0;
    int jend = PRE_NMS - j0; if (jend > 64) jend = 64;
    for (int jj = 0; jj < jend; jj++) {
        float4 bj = sj[jj];
        float areaJ = (bj.z - bj.x + 1.f) * (bj.w - bj.y + 1.f);
        float iw = fminf(bi.z, bj.z) - fmaxf(bi.x, bj.x) + 1.f;
        float ih = fminf(bi.w, bj.w) - fmaxf(bi.y, bj.y) + 1.f;
        iw = fmaxf(iw, 0.f); ih = fmaxf(ih, 0.f);
        float inter = iw * ih;
        float iou = inter / (areaJ + areaI - inter);
        if (iou > NMS_TH) m |= (1ULL << jj);
    }
    g_iou[(size_t)i * NWORDS + wb] = m;
}

// ---------------- single-warp greedy NMS with 16-way row prefetch ----------------
__global__ void nms_kernel() {
    int lane = threadIdx.x;
    unsigned long long rem0 = 0, rem1 = 0, rem2 = 0;
    int w2 = lane + 64;
    if (w2 == 93) rem2 = ~((1ULL << 48) - 1ULL);
    else if (w2 > 93) rem2 = ~0ULL;
    int nk = 0;
    while (nk < POST_NMS) {
        unsigned long long a0 = ~rem0, a1 = ~rem1, a2 = ~rem2;
        int cand[16];
#pragma unroll
        for (int t = 0; t < 16; t++) cand[t] = -1;
#pragma unroll
        for (int t = 0; t < 16; t++) {
            unsigned b0 = __ballot_sync(0xffffffffu, a0 != 0ULL);
            unsigned b1 = __ballot_sync(0xffffffffu, a1 != 0ULL);
            unsigned b2 = __ballot_sync(0xffffffffu, a2 != 0ULL);
            int slot = -1, src = 0;
            if (b0) { slot = 0; src = __ffs(b0) - 1; }
            else if (b1) { slot = 1; src = __ffs(b1) - 1; }
            else if (b2) { slot = 2; src = __ffs(b2) - 1; }
            if (slot < 0) break;
            unsigned long long mysel = (slot == 0) ? a0 : ((slot == 1) ? a1 : a2);
            int mybit = __ffsll((long long)mysel) - 1;
            int bit = __shfl_sync(0xffffffffu, mybit, src);
            cand[t] = (slot * 32 + src) * 64 + bit;
            if (lane == src) {
                if (slot == 0) a0 &= (a0 - 1);
                else if (slot == 1) a1 &= (a1 - 1);
                else a2 &= (a2 - 1);
            }
        }
        if (cand[0] < 0) break;
        unsigned long long r[16][3];
#pragma unroll
        for (int t = 0; t < 16; t++) {
            if (cand[t] >= 0) {
                const unsigned long long* row = g_iou + (size_t)cand[t] * NWORDS;
                r[t][0] = __ldg(row + lane);
                r[t][1] = __ldg(row + lane + 32);
                r[t][2] = (w2 < NWORDS) ? __ldg(row + w2) : 0ULL;
            } else {
                r[t][0] = r[t][1] = r[t][2] = 0ULL;
            }
        }
#pragma unroll
        for (int t = 0; t < 16; t++) {
            int idx = cand[t];
            if (idx < 0 || nk >= POST_NMS) break;
            if (t > 0) {
                int w = idx >> 6, b = idx & 63;
                unsigned long long mine = (w < 32) ? rem0 : ((w < 64) ? rem1 : rem2);
                unsigned long long ow = __shfl_sync(0xffffffffu, mine, w & 31);
                if ((ow >> b) & 1ULL) continue;
            }
            if (lane == 0) g_keep[nk] = idx;
            nk++;
            rem0 |= r[t][0]; rem1 |= r[t][1]; rem2 |= r[t][2];
        }
    }
    if (lane == 0) g_numKeep = nk;
}

// ---------------- assemble output (1000 x 6) ----------------
__global__ void output_kernel(float* __restrict__ out) {
    int i = blockIdx.x * blockDim.x + threadIdx.x;
    if (i >= POST_NMS) return;
    float x1 = 0, y1 = 0, x2 = 0, y2 = 0, s = 0;
    int nk = g_numKeep;
    if (i < nk) {
        int k = g_keep[i];
        x1 = g_boxes[k * 4 + 0]; y1 = g_boxes[k * 4 + 1];
        x2 = g_boxes[k * 4 + 2]; y2 = g_boxes[k * 4 + 3];
        s = g_selScore[k];
    }
    out[i * 6 + 0] = 0.f;
    out[i * 6 + 1] = x1;
    out[i * 6 + 2] = y1;
    out[i * 6 + 3] = x2;
    out[i * 6 + 4] = y2;
    out[i * 6 + 5] = s;
}

// ---------------- launch ----------------
extern "C" void kernel_launch(void* const* d_in, const int* in_sizes, int n_in,
                              void* d_out, int out_size) {
    const float* feats[5];
    for (int i = 0; i < 5; i++) feats[i] = (const float*)d_in[i];
    const float* im_info = (const float*)d_in[5];
    const float* convW = (const float*)d_in[6];
    const float* convB = (const float*)d_in[7];
    const float* sw = (const float*)d_in[8];
    const float* sb = (const float*)d_in[9];
    const float* bw = (const float*)d_in[10];
    const float* bb = (const float*)d_in[11];
    float* out = (float*)d_out;

    static bool attrDone = false;
    if (!attrDone) {
        cudaFuncSetAttribute(sort_kernel,
                             cudaFuncAttributeMaxDynamicSharedMemorySize, CAND_MAX * 8);
        attrDone = true;
    }

    prep_kernel<<<dim3(1109, 8), dim3(32, 32)>>>(feats[0], feats[1], feats[2],
                                                 feats[3], feats[4]);
    repackw_kernel<<<(512 * 2304 + 255) / 256, 256>>>(convW);
    fold_kernel<<<(2304 * 3 + 255) / 256, 256>>>(sw, sb, convB);
    approx_score_kernel<<<1109, 256>>>();
    select16_kernel<<<1, 1024>>>(POOL_K);
    mark_compact_kernel<<<416, 256>>>();
    exact_conv_kernel<<<dim3(256, 2), 256>>>(convB);
    heads_pool_kernel<<<128, 256>>>(sw, sb, bw, bb);
    compact_kernel<<<416, 256>>>();
    sort_kernel<<<1, 1024, CAND_MAX * 8>>>();
    decode_kernel<<<(PRE_NMS + 255) / 256, 256>>>(im_info);
    iou_kernel<<<dim3(94, 94), 64>>>();
    nms_kernel<<<1, 32>>>();
    output_kernel<<<(POST_NMS + 255) / 256, 256>>>(out);
}

// round 15
// speedup vs baseline: 1.1383x; 1.0124x over previous
#include <cuda_runtime.h>
#include <math.h>
#include <stdint.h>

#define NPIX 35464
#define NANCH 106392
#define PRE_NMS 6000
#define POOL_K 6656
#define POOLMAX 8192
#define POST_NMS 1000
#define NMS_TH 0.7f
#define CAND_MAX 8192
#define NWORDS 94    // ceil(6000/64)

// ---------------- device scratch ----------------
__device__ float g_f[(size_t)NPIX * 512];     // exact features (pool pixels only)
__device__ float g_fp[(size_t)NPIX * 256];    // fp32 input, pixel-major
__device__ float g_wT[2304 * 512];            // fp32 conv weights [k][oc]
__device__ float g_wd[2304 * 3];              // folded diff weights [k][a]
__device__ float g_wdB[3];                    // folded diff bias
__device__ unsigned g_keys[NANCH];            // approx, then exact for pool anchors
__device__ unsigned g_keysA[NANCH];           // approx keys (filter copy)
__device__ float g_deltas[(size_t)NANCH * 4];
__device__ unsigned g_hist16[65536];
__device__ unsigned g_prefix;
__device__ int g_candCount;
__device__ unsigned long long g_cand[CAND_MAX];
__device__ int g_pixFlag[NPIX];
__device__ int g_poolPix[POOLMAX];
__device__ int g_poolCnt;
__device__ float g_selScore[PRE_NMS];
__device__ float g_boxes[PRE_NMS * 4];
__device__ unsigned long long g_iou[(size_t)PRE_NMS * NWORDS];
__device__ int g_keep[POST_NMS];
__device__ int g_numKeep;

// constants
__constant__ int c_aoff[6] = {0, 79872, 99840, 104832, 106080, 106392};
__constant__ int c_W[5] = {208, 104, 52, 26, 13};
__constant__ int c_H[5] = {128, 64, 32, 16, 8};
__constant__ int c_stride[5] = {4, 8, 16, 32, 64};
__constant__ int c_pixBase[5] = {0, 26624, 33280, 34944, 35360};
__constant__ int c_ws0[15] = {6,4,3, 11,8,6, 23,16,11, 45,32,23, 91,64,45};
__constant__ int c_hs0[15] = {3,4,6, 6,8,12, 12,16,22, 22,32,46, 46,64,90};

// ---------------- f32x2 helpers (per-component == fma.rn.f32, bit-exact) ----------------
__device__ __forceinline__ void ffma2(unsigned long long& c, unsigned long long a,
                                      unsigned long long b) {
    asm("fma.rn.f32x2 %0, %1, %2, %3;" : "=l"(c) : "l"(a), "l"(b), "l"(c));
}
__device__ __forceinline__ unsigned long long pack2(float x, float y) {
    unsigned long long r;
    asm("mov.b64 %0, {%1, %2};" : "=l"(r) : "f"(x), "f"(y));
    return r;
}
__device__ __forceinline__ float2 unpack2(unsigned long long v) {
    float2 r;
    asm("mov.b64 {%0, %1}, %2;" : "=f"(r.x), "=f"(r.y) : "l"(v));
    return r;
}

// ---------------- prep (all 5 levels fused): NCHW fp32 -> pixel-major fp32 ----------------
__global__ void prep_kernel(const float* __restrict__ p2, const float* __restrict__ p3,
                            const float* __restrict__ p4, const float* __restrict__ p5,
                            const float* __restrict__ p6) {
    __shared__ float sh[32][33];
    int g0 = blockIdx.x * 32;
    int l = 0;
    while (l < 4 && g0 >= c_pixBase[l + 1]) l++;
    const float* f = (l == 0) ? p2 : (l == 1) ? p3 : (l == 2) ? p4 : (l == 3) ? p5 : p6;
    int HW = c_W[l] * c_H[l];
    int base = c_pixBase[l];
    int ic0 = blockIdx.y * 32;
    int tx = threadIdx.x, ty = threadIdx.y;
    int p = g0 - base + tx;
    sh[ty][tx] = (p < HW) ? f[(size_t)(ic0 + ty) * HW + p] : 0.f;
    __syncthreads();
    int pw = g0 - base + ty;
    if (pw < HW)
        g_fp[(size_t)(base + pw) * 256 + ic0 + tx] = sh[tx][ty];
}

// ---------------- weight transpose + zero scratch ----------------
__global__ void repackw_kernel(const float* __restrict__ w) {
    int t = blockIdx.x * blockDim.x + threadIdx.x;
    if (t < 65536) g_hist16[t] = 0;
    if (t < NPIX) g_pixFlag[t] = 0;
    if (t == 0) { g_candCount = 0; g_numKeep = 0; g_poolCnt = 0; }
    if (t >= 512 * 2304) return;
    int oc = t / 2304, k = t - oc * 2304;
    int tap = k >> 8, ic = k & 255;
    g_wT[k * 512 + oc] = w[oc * 2304 + ic * 9 + tap];
}

// ---------------- fold score-diff head into conv: wd[k][a] = Weff[k][3+a]-Weff[k][a] ----------------
__global__ void fold_kernel(const float* __restrict__ sw, const float* __restrict__ sb,
                            const float* __restrict__ convB) {
    int t = blockIdx.x * blockDim.x + threadIdx.x;
    if (t < 3) {
        float acc = sb[3 + t] - sb[t];
        for (int oc = 0; oc < 512; oc++)
            acc += (sw[(3 + t) * 512 + oc] - sw[t * 512 + oc]) * convB[oc];
        g_wdB[t] = acc;
    }
    if (t >= 2304 * 3) return;
    int k = t / 3, a = t - k * 3;
    const float4* wr = (const float4*)(g_wT + (size_t)k * 512);
    const float4* s0 = (const float4*)(sw + a * 512);
    const float4* s1 = (const float4*)(sw + (3 + a) * 512);
    float acc = 0.f;
#pragma unroll 4
    for (int q = 0; q < 128; q++) {
        float4 wv = wr[q];
        float4 b0 = s0[q], b1 = s1[q];
        acc += wv.x * (b1.x - b0.x) + wv.y * (b1.y - b0.y)
             + wv.z * (b1.z - b0.z) + wv.w * (b1.w - b0.w);
    }
    g_wd[t] = acc;
}

// ---------------- approx scores + fused histogram ----------------
// swizzled smem layout: addr(k) = k*4 + (k>>3)*4 floats -> conflict-free LDS.128
__global__ void __launch_bounds__(256) approx_score_kernel() {
    __shared__ float s_wd[2304 * 4 + 288 * 4];   // 41472 B
    __shared__ float s_bd[3];
    int tid = threadIdx.x;
    for (int k = tid; k < 2304; k += 256) {
        int base = k * 4 + (k >> 3) * 4;
        s_wd[base + 0] = g_wd[k * 3 + 0];
        s_wd[base + 1] = g_wd[k * 3 + 1];
        s_wd[base + 2] = g_wd[k * 3 + 2];
        s_wd[base + 3] = 0.f;
    }
    if (tid < 3) s_bd[tid] = g_wdB[tid];
    __syncthreads();
    int lane = tid & 31;
    const int ic0 = lane * 8;
    for (int p = 0; p < 4; p++) {
        int gw = blockIdx.x * 32 + (tid >> 5) * 4 + p;
        if (gw >= NPIX) break;
        int l = 0;
        while (l < 4 && gw >= c_pixBase[l + 1]) l++;
        const int Wl = c_W[l], Hl = c_H[l];
        int local = gw - c_pixBase[l];
        int py = local / Wl, px = local - py * Wl;
        float d0 = 0.f, d1 = 0.f, d2 = 0.f;
#pragma unroll
        for (int tap = 0; tap < 9; tap++) {
            int dy = tap / 3 - 1, dx = tap % 3 - 1;
            int iy = py + dy, ix = px + dx;
            if ((unsigned)iy >= (unsigned)Hl || (unsigned)ix >= (unsigned)Wl) continue;
            const float* src = g_fp + ((size_t)(c_pixBase[l] + iy * Wl + ix)) * 256 + ic0;
            float4 v0 = *(const float4*)src;
            float4 v1 = *(const float4*)(src + 4);
            float a[8] = {v0.x, v0.y, v0.z, v0.w, v1.x, v1.y, v1.z, v1.w};
            const float* wp = s_wd + tap * 1152 + lane * 36;
#pragma unroll
            for (int j = 0; j < 8; j++) {
                float4 wd = *(const float4*)(wp + j * 4);
                d0 = fmaf(a[j], wd.x, d0);
                d1 = fmaf(a[j], wd.y, d1);
                d2 = fmaf(a[j], wd.z, d2);
            }
        }
#pragma unroll
        for (int off = 16; off; off >>= 1) {
            d0 += __shfl_xor_sync(0xffffffffu, d0, off);
            d1 += __shfl_xor_sync(0xffffffffu, d1, off);
            d2 += __shfl_xor_sync(0xffffffffu, d2, off);
        }
        if (lane < 3) {
            float D = (lane == 0 ? d0 : (lane == 1 ? d1 : d2)) + s_bd[lane];
            float s = 1.f / (1.f + expf(-D));
            unsigned bits = __float_as_uint(s);
            unsigned key = bits ^ ((unsigned)((int)bits >> 31) | 0x80000000u);
            g_keys[gw * 3 + lane] = key;
            g_keysA[gw * 3 + lane] = key;
            atomicAdd(&g_hist16[key >> 16], 1u);
        }
    }
}

// single block, 1024 threads, register-light: two streaming passes over g_hist16
__global__ void __launch_bounds__(1024) select16_kernel(int K) {
    __shared__ unsigned tot[1024];
    int t = threadIdx.x;
    int b0 = t * 64;
    unsigned sum = 0;
    for (int i = 0; i < 64; i++) sum += g_hist16[b0 + i];
    tot[t] = sum;
    __syncthreads();
    for (int d = 1; d < 1024; d <<= 1) {
        unsigned v = (t + d < 1024) ? tot[t + d] : 0u;
        __syncthreads();
        tot[t] += v;
        __syncthreads();
    }
    unsigned suffAfter = (t < 1023) ? tot[t + 1] : 0u;
    if (tot[t] >= (unsigned)K && suffAfter < (unsigned)K) {
        unsigned run = suffAfter;
        for (int i = 63; i >= 0; i--) {
            unsigned before = run;
            run += g_hist16[b0 + i];
            if (run >= (unsigned)K && before < (unsigned)K) {
                g_prefix = ((unsigned)(b0 + i)) << 16;
                break;
            }
        }
    }
}

// ---------------- pool marking ----------------
__global__ void mark_compact_kernel() {
    unsigned T = g_prefix;
    for (int i = blockIdx.x * blockDim.x + threadIdx.x; i < NANCH;
         i += gridDim.x * blockDim.x) {
        if (g_keysA[i] >= T) {
            int pix = i / 3;
            if (atomicExch(&g_pixFlag[pix], 1) == 0) {
                int p = atomicAdd(&g_poolCnt, 1);
                if (p < POOLMAX) g_poolPix[p] = pix;
            }
        }
    }
}

// ---------------- exact fp32 recompute of pool pixels (R1-identical chain, FFMA2) ----------------
// grid (256, 2), 256 threads. Tile: 32 pixels x 256 oc. Thread: 4 px x 8 oc (4 pairs).
__global__ void __launch_bounds__(256) exact_conv_kernel(const float* __restrict__ bias) {
    __shared__ float sA[32][33];
    __shared__ float sW[32][264];
    __shared__ int s_pix[32], s_base[32], s_W[32], s_H[32], s_py[32], s_px[32];

    const int tid = threadIdx.x;
    const int cnt = g_poolCnt < POOLMAX ? g_poolCnt : POOLMAX;
    const int ptile = blockIdx.x;
    if (ptile * 32 >= cnt) return;
    const int oc0 = blockIdx.y * 256;

    if (tid < 32) {
        int idx = ptile * 32 + tid;
        int pix = (idx < cnt) ? g_poolPix[idx] : -1;
        s_pix[tid] = pix;
        if (pix >= 0) {
            int l = 0;
            while (l < 4 && pix >= c_pixBase[l + 1]) l++;
            int local = pix - c_pixBase[l];
            int Wl = c_W[l];
            s_base[tid] = c_pixBase[l];
            s_W[tid] = Wl;
            s_H[tid] = c_H[l];
            s_py[tid] = local / Wl;
            s_px[tid] = local - (local / Wl) * Wl;
        }
    }
    __syncthreads();

    const int lane = tid & 31, wid = tid >> 5;
    const int ocL = wid * 32 + (lane >> 3) * 8;
    const int p0 = (lane & 7) * 4;

    const int ap = tid >> 3;
    const int akq = (tid & 7) * 4;
    const int wkk = tid >> 6;
    const int woc = (tid & 63) * 4;

    // acc pairs: [pixel][oc-pair], component = (ocL + pair*2 + {0,1})
    unsigned long long acc2[4][4];
#pragma unroll
    for (int i = 0; i < 4; i++)
#pragma unroll
        for (int j = 0; j < 4; j++) acc2[i][j] = 0ULL;

    for (int chunk = 0; chunk < 72; chunk++) {
        const int tap = chunk >> 3;
        const int ic0 = (chunk & 7) * 32;
        const int dy = tap / 3 - 1;
        const int dx = tap - (tap / 3) * 3 - 1;
        const int k0 = chunk * 32;
        {
            float4 val = make_float4(0.f, 0.f, 0.f, 0.f);
            int pix = s_pix[ap];
            if (pix >= 0) {
                int iy = s_py[ap] + dy, ix = s_px[ap] + dx;
                if ((unsigned)iy < (unsigned)s_H[ap] && (unsigned)ix < (unsigned)s_W[ap]) {
                    int np = s_base[ap] + iy * s_W[ap] + ix;
                    val = *(const float4*)(g_fp + (size_t)np * 256 + ic0 + akq);
                }
            }
            sA[ap][akq + 0] = val.x;
            sA[ap][akq + 1] = val.y;
            sA[ap][akq + 2] = val.z;
            sA[ap][akq + 3] = val.w;
        }
#pragma unroll
        for (int r = 0; r < 8; r++) {
            int kk = r * 4 + wkk;
            *(float4*)&sW[kk][woc] =
                *(const float4*)(g_wT + (size_t)(k0 + kk) * 512 + oc0 + woc);
        }
        __syncthreads();
#pragma unroll 8
        for (int kk = 0; kk < 32; kk++) {
            unsigned long long a0 = pack2(sA[p0 + 0][kk], sA[p0 + 0][kk]);
            unsigned long long a1 = pack2(sA[p0 + 1][kk], sA[p0 + 1][kk]);
            unsigned long long a2 = pack2(sA[p0 + 2][kk], sA[p0 + 2][kk]);
            unsigned long long a3 = pack2(sA[p0 + 3][kk], sA[p0 + 3][kk]);
#pragma unroll
            for (int jp = 0; jp < 4; jp++) {
                float2 wp = *(const float2*)&sW[kk][ocL + jp * 2];
                unsigned long long w2 = pack2(wp.x, wp.y);
                ffma2(acc2[0][jp], a0, w2);
                ffma2(acc2[1][jp], a1, w2);
                ffma2(acc2[2][jp], a2, w2);
                ffma2(acc2[3][jp], a3, w2);
            }
        }
        __syncthreads();
    }

#pragma unroll
    for (int i = 0; i < 4; i++) {
        int pix = s_pix[p0 + i];
        if (pix >= 0) {
            float* o = g_f + (size_t)pix * 512 + oc0 + ocL;
#pragma unroll
            for (int jp = 0; jp < 4; jp++) {
                float2 r = unpack2(acc2[i][jp]);
                o[jp * 2 + 0] = r.x + bias[oc0 + ocL + jp * 2 + 0];
                o[jp * 2 + 1] = r.y + bias[oc0 + ocL + jp * 2 + 1];
            }
        }
    }
}

// ---------------- exact heads on pool pixels (R1-identical, weights staged in smem) ----------------
__device__ __forceinline__ void heads_pixel(int gw, int lane,
        const float* __restrict__ sw, const float* __restrict__ sb,
        const float* __restrict__ bw, const float* __restrict__ bb)
{
    const float* f = g_f + (size_t)gw * 512;
    float4 v[4];
#pragma unroll
    for (int j = 0; j < 4; j++)
        v[j] = *(const float4*)(f + j * 128 + lane * 4);

    float c[6];
#pragma unroll
    for (int ch = 0; ch < 6; ch++) {
        const float* w = sw + ch * 512;
        float s = 0.f;
#pragma unroll
        for (int j = 0; j < 4; j++) {
            float4 ww = *(const float4*)(w + j * 128 + lane * 4);
            s += v[j].x * ww.x + v[j].y * ww.y + v[j].z * ww.z + v[j].w * ww.w;
        }
#pragma unroll
        for (int off = 16; off; off >>= 1) s += __shfl_xor_sync(0xffffffffu, s, off);
        c[ch] = s + sb[ch];
    }
    float d[12];
#pragma unroll
    for (int ch = 0; ch < 12; ch++) {
        const float* w = bw + ch * 512;
        float s = 0.f;
#pragma unroll
        for (int j = 0; j < 4; j++) {
            float4 ww = *(const float4*)(w + j * 128 + lane * 4);
            s += v[j].x * ww.x + v[j].y * ww.y + v[j].z * ww.z + v[j].w * ww.w;
        }
#pragma unroll
        for (int off = 16; off; off >>= 1) s += __shfl_xor_sync(0xffffffffu, s, off);
        d[ch] = s + bb[ch];
    }
    int base = gw * 3;
    if (lane < 3) {
        float s = 1.f / (1.f + expf(c[lane] - c[3 + lane]));
        unsigned bits = __float_as_uint(s);
        unsigned key = bits ^ ((unsigned)((int)bits >> 31) | 0x80000000u);
        g_keys[base + lane] = key;
    }
    if (lane < 12) {
        g_deltas[(size_t)base * 4 + lane] = d[lane];
    }
}

__global__ void __launch_bounds__(256) heads_pool_kernel(
        const float* __restrict__ sw, const float* __restrict__ sb,
        const float* __restrict__ bw, const float* __restrict__ bb)
{
    __shared__ __align__(16) float s_sw[6 * 512];
    __shared__ __align__(16) float s_bw[12 * 512];
    int tid = threadIdx.x;
    for (int i = tid; i < 6 * 512 / 4; i += 256)
        ((float4*)s_sw)[i] = ((const float4*)sw)[i];
    for (int i = tid; i < 12 * 512 / 4; i += 256)
        ((float4*)s_bw)[i] = ((const float4*)bw)[i];
    __syncthreads();
    int lane = tid & 31, wid = tid >> 5;
    int cnt = g_poolCnt < POOLMAX ? g_poolCnt : POOLMAX;
    for (int i = blockIdx.x * 8 + wid; i < cnt; i += gridDim.x * 8)
        heads_pixel(g_poolPix[i], lane, s_sw, sb, s_bw, bb);
}

// ---------------- compact: filter by approx key, payload exact key ----------------
__global__ void compact_kernel() {
    unsigned T = g_prefix;
    for (int i = blockIdx.x * blockDim.x + threadIdx.x; i < NANCH;
         i += gridDim.x * blockDim.x) {
        if (g_keysA[i] >= T) {
            unsigned k = g_keys[i];   // exact (pixel is in pool by construction)
            int p = atomicAdd(&g_candCount, 1);
            if (p < CAND_MAX)
                g_cand[p] = ((unsigned long long)k << 32) | (unsigned)(~i);
        }
    }
}

// ---------------- bitonic sort + fused decode (key desc, idx asc) ----------------
__global__ void sort_kernel(const float* __restrict__ im_info) {
    extern __shared__ unsigned long long s[];
    int tid = threadIdx.x;
    int cnt = g_candCount;
    if (cnt > CAND_MAX) cnt = CAND_MAX;
    for (int i = tid; i < CAND_MAX; i += blockDim.x)
        s[i] = (i < cnt) ? g_cand[i] : 0ULL;
    __syncthreads();
    for (int k = 2; k <= CAND_MAX; k <<= 1) {
        for (int j = k >> 1; j > 0; j >>= 1) {
            for (int i = tid; i < CAND_MAX; i += blockDim.x) {
                int ixj = i ^ j;
                if (ixj > i) {
                    unsigned long long a = s[i], b = s[ixj];
                    bool desc = ((i & k) == 0);
                    if (desc ? (a < b) : (a > b)) { s[i] = b; s[ixj] = a; }
                }
            }
            __syncthreads();
        }
    }
    float imW = im_info[1] - 1.f, imH = im_info[0] - 1.f;
    for (int i = tid; i < PRE_NMS; i += blockDim.x) {
        unsigned long long e = s[i];
        unsigned idx = ~(unsigned)(e & 0xffffffffu);
        unsigned key = (unsigned)(e >> 32);
        unsigned bits = (key & 0x80000000u) ? (key ^ 0x80000000u) : ~key;
        g_selScore[i] = __uint_as_float(bits);
        // ---- decode (identical arithmetic to R13 decode_kernel) ----
        int id = (int)idx;
        int l = 0;
        while (l < 4 && id >= c_aoff[l + 1]) l++;
        int local = id - c_aoff[l];
        int p = local / 3, a = local - p * 3;
        int W = c_W[l];
        int y = p / W, x = p - y * W;
        float stride = (float)c_stride[l];
        float cb = (stride - 1.f) * 0.5f;
        float ws = c_ws0[l * 3 + a] * 8.f, hs = c_hs0[l * 3 + a] * 8.f;
        float sx = x * stride, sy = y * stride;
        float ax1 = sx + cb - 0.5f * (ws - 1.f);
        float ay1 = sy + cb - 0.5f * (hs - 1.f);
        float ax2 = sx + cb + 0.5f * (ws - 1.f);
        float ay2 = sy + cb + 0.5f * (hs - 1.f);
        float w = ax2 - ax1 + 1.f, h = ay2 - ay1 + 1.f;
        float cx = ax1 + 0.5f * w, cy = ay1 + 0.5f * h;
        const float* dd = g_deltas + (size_t)id * 4;
        float pcx = dd[0] * w + cx;
        float pcy = dd[1] * h + cy;
        float pw = expf(dd[2]) * w;
        float ph = expf(dd[3]) * h;
        g_boxes[i * 4 + 0] = fminf(fmaxf(pcx - 0.5f * pw, 0.f), imW);
        g_boxes[i * 4 + 1] = fminf(fmaxf(pcy - 0.5f * ph, 0.f), imH);
        g_boxes[i * 4 + 2] = fminf(fmaxf(pcx + 0.5f * pw, 0.f), imW);
        g_boxes[i * 4 + 3] = fminf(fmaxf(pcy + 0.5f * ph, 0.f), imH);
    }
}

// ---------------- IoU suppression bitmask (smem-tiled) ----------------
__global__ void iou_kernel() {
    __shared__ float4 sj[64];
    int wb = blockIdx.y;
    int t = threadIdx.x;
    int j0 = wb * 64;
    {
        int j = j0 + t;
        sj[t] = (j < PRE_NMS) ? ((const float4*)g_boxes)[j]
                              : make_float4(0.f, 0.f, 0.f, 0.f);
    }
    __syncthreads();
    int i = blockIdx.x * 64 + t;
    if (i >= PRE_NMS) return;
    float4 bi = ((const float4*)g_boxes)[i];
    float areaI = (bi.z - bi.x + 1.f) * (bi.w - bi.y + 1.f);
    unsigned long long m = 0;
    int jend = PRE_NMS - j0; if (jend > 64) jend = 64;
    for (int jj = 0; jj < jend; jj++) {
        float4 bj = sj[jj];
        float areaJ = (bj.z - bj.x + 1.f) * (bj.w - bj.y + 1.f);
        float iw = fminf(bi.z, bj.z) - fmaxf(bi.x, bj.x) + 1.f;
        float ih = fminf(bi.w, bj.w) - fmaxf(bi.y, bj.y) + 1.f;
        iw = fmaxf(iw, 0.f); ih = fmaxf(ih, 0.f);
        float inter = iw * ih;
        float iou = inter / (areaJ + areaI - inter);
        if (iou > NMS_TH) m |= (1ULL << jj);
    }
    g_iou[(size_t)i * NWORDS + wb] = m;
}

// ---------------- single-warp greedy NMS with 16-way row prefetch ----------------
__global__ void nms_kernel() {
    int lane = threadIdx.x;
    unsigned long long rem0 = 0, rem1 = 0, rem2 = 0;
    int w2 = lane + 64;
    if (w2 == 93) rem2 = ~((1ULL << 48) - 1ULL);
    else if (w2 > 93) rem2 = ~0ULL;
    int nk = 0;
    while (nk < POST_NMS) {
        unsigned long long a0 = ~rem0, a1 = ~rem1, a2 = ~rem2;
        int cand[16];
#pragma unroll
        for (int t = 0; t < 16; t++) cand[t] = -1;
#pragma unroll
        for (int t = 0; t < 16; t++) {
            unsigned b0 = __ballot_sync(0xffffffffu, a0 != 0ULL);
            unsigned b1 = __ballot_sync(0xffffffffu, a1 != 0ULL);
            unsigned b2 = __ballot_sync(0xffffffffu, a2 != 0ULL);
            int slot = -1, src = 0;
            if (b0) { slot = 0; src = __ffs(b0) - 1; }
            else if (b1) { slot = 1; src = __ffs(b1) - 1; }
            else if (b2) { slot = 2; src = __ffs(b2) - 1; }
            if (slot < 0) break;
            unsigned long long mysel = (slot == 0) ? a0 : ((slot == 1) ? a1 : a2);
            int mybit = __ffsll((long long)mysel) - 1;
            int bit = __shfl_sync(0xffffffffu, mybit, src);
            cand[t] = (slot * 32 + src) * 64 + bit;
            if (lane == src) {
                if (slot == 0) a0 &= (a0 - 1);
                else if (slot == 1) a1 &= (a1 - 1);
                else a2 &= (a2 - 1);
            }
        }
        if (cand[0] < 0) break;
        unsigned long long r[16][3];
#pragma unroll
        for (int t = 0; t < 16; t++) {
            if (cand[t] >= 0) {
                const unsigned long long* row = g_iou + (size_t)cand[t] * NWORDS;
                r[t][0] = __ldg(row + lane);
                r[t][1] = __ldg(row + lane + 32);
                r[t][2] = (w2 < NWORDS) ? __ldg(row + w2) : 0ULL;
            } else {
                r[t][0] = r[t][1] = r[t][2] = 0ULL;
            }
        }
#pragma unroll
        for (int t = 0; t < 16; t++) {
            int idx = cand[t];
            if (idx < 0 || nk >= POST_NMS) break;
            if (t > 0) {
                int w = idx >> 6, b = idx & 63;
                unsigned long long mine = (w < 32) ? rem0 : ((w < 64) ? rem1 : rem2);
                unsigned long long ow = __shfl_sync(0xffffffffu, mine, w & 31);
                if ((ow >> b) & 1ULL) continue;
            }
            if (lane == 0) g_keep[nk] = idx;
            nk++;
            rem0 |= r[t][0]; rem1 |= r[t][1]; rem2 |= r[t][2];
        }
    }
    if (lane == 0) g_numKeep = nk;
}

// ---------------- assemble output (1000 x 6) ----------------
__global__ void output_kernel(float* __restrict__ out) {
    int i = blockIdx.x * blockDim.x + threadIdx.x;
    if (i >= POST_NMS) return;
    float x1 = 0, y1 = 0, x2 = 0, y2 = 0, s = 0;
    int nk = g_numKeep;
    if (i < nk) {
        int k = g_keep[i];
        x1 = g_boxes[k * 4 + 0]; y1 = g_boxes[k * 4 + 1];
        x2 = g_boxes[k * 4 + 2]; y2 = g_boxes[k * 4 + 3];
        s = g_selScore[k];
    }
    out[i * 6 + 0] = 0.f;
    out[i * 6 + 1] = x1;
    out[i * 6 + 2] = y1;
    out[i * 6 + 3] = x2;
    out[i * 6 + 4] = y2;
    out[i * 6 + 5] = s;
}

// ---------------- launch ----------------
extern "C" void kernel_launch(void* const* d_in, const int* in_sizes, int n_in,
                              void* d_out, int out_size) {
    const float* feats[5];
    for (int i = 0; i < 5; i++) feats[i] = (const float*)d_in[i];
    const float* im_info = (const float*)d_in[5];
    const float* convW = (const float*)d_in[6];
    const float* convB = (const float*)d_in[7];
    const float* sw = (const float*)d_in[8];
    const float* sb = (const float*)d_in[9];
    const float* bw = (const float*)d_in[10];
    const float* bb = (const float*)d_in[11];
    float* out = (float*)d_out;

    static bool attrDone = false;
    if (!attrDone) {
        cudaFuncSetAttribute(sort_kernel,
                             cudaFuncAttributeMaxDynamicSharedMemorySize, CAND_MAX * 8);
        attrDone = true;
    }

    prep_kernel<<<dim3(1109, 8), dim3(32, 32)>>>(feats[0], feats[1], feats[2],
                                                 feats[3], feats[4]);
    repackw_kernel<<<(512 * 2304 + 255) / 256, 256>>>(convW);
    fold_kernel<<<(2304 * 3 + 255) / 256, 256>>>(sw, sb, convB);
    approx_score_kernel<<<1109, 256>>>();
    select16_kernel<<<1, 1024>>>(POOL_K);
    mark_compact_kernel<<<416, 256>>>();
    exact_conv_kernel<<<dim3(256, 2), 256>>>(convB);
    heads_pool_kernel<<<128, 256>>>(sw, sb, bw, bb);
    compact_kernel<<<416, 256>>>();
    sort_kernel<<<1, 1024, CAND_MAX * 8>>>(im_info);
    iou_kernel<<<dim3(94, 94), 64>>>();
    nms_kernel<<<1, 32>>>();
    output_kernel<<<(POST_NMS + 255) / 256, 256>>>(out);
}

// round 16
// speedup vs baseline: 1.2042x; 1.0579x over previous
#include <cuda_runtime.h>
#include <math.h>
#include <stdint.h>

#define NPIX 35464
#define NANCH 106392
#define PRE_NMS 6000
#define POOL_K 6656
#define POOLMAX 8192
#define POST_NMS 1000
#define NMS_TH 0.7f
#define CAND_MAX 8192
#define NWORDS 94    // ceil(6000/64)

// ---------------- device scratch ----------------
__device__ float g_f[(size_t)NPIX * 512];     // exact features (pool pixels only)
__device__ float g_fp[(size_t)NPIX * 256];    // fp32 input, pixel-major
__device__ float g_wT[2304 * 512];            // fp32 conv weights [k][oc]
__device__ float g_wd[2304 * 3];              // folded diff weights [k][a]
__device__ float g_wdB[3];                    // folded diff bias
__device__ unsigned g_keys[NANCH];            // approx, then exact for pool anchors
__device__ float g_deltas[(size_t)NANCH * 4];
__device__ unsigned g_hist16[65536];
__device__ unsigned g_prefix;
__device__ int g_candCount;
__device__ int g_candIdx[CAND_MAX];
__device__ unsigned long long g_cand[CAND_MAX];
__device__ int g_pixFlag[NPIX];
__device__ int g_poolPix[POOLMAX];
__device__ int g_poolCnt;
__device__ float g_selScore[PRE_NMS];
__device__ float g_boxes[PRE_NMS * 4];
__device__ unsigned long long g_iou[(size_t)PRE_NMS * NWORDS];
__device__ int g_keep[POST_NMS];
__device__ int g_numKeep;

// constants
__constant__ int c_aoff[6] = {0, 79872, 99840, 104832, 106080, 106392};
__constant__ int c_W[5] = {208, 104, 52, 26, 13};
__constant__ int c_H[5] = {128, 64, 32, 16, 8};
__constant__ int c_stride[5] = {4, 8, 16, 32, 64};
__constant__ int c_pixBase[5] = {0, 26624, 33280, 34944, 35360};
__constant__ int c_ws0[15] = {6,4,3, 11,8,6, 23,16,11, 45,32,23, 91,64,45};
__constant__ int c_hs0[15] = {3,4,6, 6,8,12, 12,16,22, 22,32,46, 46,64,90};

// ---------------- f32x2 helpers (per-component == fma.rn.f32, bit-exact) ----------------
__device__ __forceinline__ void ffma2(unsigned long long& c, unsigned long long a,
                                      unsigned long long b) {
    asm("fma.rn.f32x2 %0, %1, %2, %3;" : "=l"(c) : "l"(a), "l"(b), "l"(c));
}
__device__ __forceinline__ unsigned long long pack2(float x, float y) {
    unsigned long long r;
    asm("mov.b64 %0, {%1, %2};" : "=l"(r) : "f"(x), "f"(y));
    return r;
}
__device__ __forceinline__ float2 unpack2(unsigned long long v) {
    float2 r;
    asm("mov.b64 {%0, %1}, %2;" : "=f"(r.x), "=f"(r.y) : "l"(v));
    return r;
}

// ---------------- prep (all 5 levels fused): NCHW fp32 -> pixel-major fp32 ----------------
__global__ void prep_kernel(const float* __restrict__ p2, const float* __restrict__ p3,
                            const float* __restrict__ p4, const float* __restrict__ p5,
                            const float* __restrict__ p6) {
    __shared__ float sh[32][33];
    int g0 = blockIdx.x * 32;
    int l = 0;
    while (l < 4 && g0 >= c_pixBase[l + 1]) l++;
    const float* f = (l == 0) ? p2 : (l == 1) ? p3 : (l == 2) ? p4 : (l == 3) ? p5 : p6;
    int HW = c_W[l] * c_H[l];
    int base = c_pixBase[l];
    int ic0 = blockIdx.y * 32;
    int tx = threadIdx.x, ty = threadIdx.y;
    int p = g0 - base + tx;
    sh[ty][tx] = (p < HW) ? f[(size_t)(ic0 + ty) * HW + p] : 0.f;
    __syncthreads();
    int pw = g0 - base + ty;
    if (pw < HW)
        g_fp[(size_t)(base + pw) * 256 + ic0 + tx] = sh[tx][ty];
}

// ---------------- weight transpose + zero scratch ----------------
__global__ void repackw_kernel(const float* __restrict__ w) {
    int t = blockIdx.x * blockDim.x + threadIdx.x;
    if (t < 65536) g_hist16[t] = 0;
    if (t < NPIX) g_pixFlag[t] = 0;
    if (t == 0) { g_candCount = 0; g_numKeep = 0; g_poolCnt = 0; }
    if (t >= 512 * 2304) return;
    int oc = t / 2304, k = t - oc * 2304;
    int tap = k >> 8, ic = k & 255;
    g_wT[k * 512 + oc] = w[oc * 2304 + ic * 9 + tap];
}

// ---------------- fold score-diff head into conv: wd[k][a] = Weff[k][3+a]-Weff[k][a] ----------------
__global__ void fold_kernel(const float* __restrict__ sw, const float* __restrict__ sb,
                            const float* __restrict__ convB) {
    int t = blockIdx.x * blockDim.x + threadIdx.x;
    if (t < 3) {
        float acc = sb[3 + t] - sb[t];
        for (int oc = 0; oc < 512; oc++)
            acc += (sw[(3 + t) * 512 + oc] - sw[t * 512 + oc]) * convB[oc];
        g_wdB[t] = acc;
    }
    if (t >= 2304 * 3) return;
    int k = t / 3, a = t - k * 3;
    const float4* wr = (const float4*)(g_wT + (size_t)k * 512);
    const float4* s0 = (const float4*)(sw + a * 512);
    const float4* s1 = (const float4*)(sw + (3 + a) * 512);
    float acc = 0.f;
#pragma unroll 4
    for (int q = 0; q < 128; q++) {
        float4 wv = wr[q];
        float4 b0 = s0[q], b1 = s1[q];
        acc += wv.x * (b1.x - b0.x) + wv.y * (b1.y - b0.y)
             + wv.z * (b1.z - b0.z) + wv.w * (b1.w - b0.w);
    }
    g_wd[t] = acc;
}

// ---------------- approx scores + fused histogram ----------------
// swizzled smem layout: addr(k) = k*4 + (k>>3)*4 floats -> conflict-free LDS.128
// tap-outer / j-inner: one weight LDS feeds all 4 pixels of the warp group.
__global__ void __launch_bounds__(256) approx_score_kernel() {
    __shared__ float s_wd[2304 * 4 + 288 * 4];   // 41472 B
    __shared__ float s_bd[3];
    int tid = threadIdx.x;
    for (int k = tid; k < 2304; k += 256) {
        int base = k * 4 + (k >> 3) * 4;
        s_wd[base + 0] = g_wd[k * 3 + 0];
        s_wd[base + 1] = g_wd[k * 3 + 1];
        s_wd[base + 2] = g_wd[k * 3 + 2];
        s_wd[base + 3] = 0.f;
    }
    if (tid < 3) s_bd[tid] = g_wdB[tid];
    __syncthreads();
    int lane = tid & 31;
    const int ic0 = lane * 8;
    const int gbase = blockIdx.x * 32 + (tid >> 5) * 4;

    int pb[4], pW[4], pH[4], ppy[4], ppx[4];
#pragma unroll
    for (int p = 0; p < 4; p++) {
        int gw = gbase + p;
        if (gw < NPIX) {
            int l = 0;
            while (l < 4 && gw >= c_pixBase[l + 1]) l++;
            int Wl = c_W[l];
            int local = gw - c_pixBase[l];
            pb[p] = c_pixBase[l];
            pW[p] = Wl;
            pH[p] = c_H[l];
            ppy[p] = local / Wl;
            ppx[p] = local - (local / Wl) * Wl;
        } else {
            pb[p] = 0; pW[p] = 1; pH[p] = -1; ppy[p] = -100; ppx[p] = -100;
        }
    }
    float d[4][3];
#pragma unroll
    for (int p = 0; p < 4; p++) d[p][0] = d[p][1] = d[p][2] = 0.f;

#pragma unroll
    for (int tap = 0; tap < 9; tap++) {
        int dy = tap / 3 - 1, dx = tap % 3 - 1;
        float4 a0[4], a1[4];
#pragma unroll
        for (int p = 0; p < 4; p++) {
            int iy = ppy[p] + dy, ix = ppx[p] + dx;
            if ((unsigned)iy < (unsigned)pH[p] && (unsigned)ix < (unsigned)pW[p]) {
                const float* src = g_fp + ((size_t)(pb[p] + iy * pW[p] + ix)) * 256 + ic0;
                a0[p] = *(const float4*)src;
                a1[p] = *(const float4*)(src + 4);
            } else {
                a0[p] = make_float4(0.f, 0.f, 0.f, 0.f);
                a1[p] = a0[p];
            }
        }
        const float* wp = s_wd + tap * 1152 + lane * 36;
#pragma unroll
        for (int j = 0; j < 8; j++) {
            float4 wd = *(const float4*)(wp + j * 4);
#pragma unroll
            for (int p = 0; p < 4; p++) {
                float a;
                switch (j) {
                    case 0: a = a0[p].x; break;
                    case 1: a = a0[p].y; break;
                    case 2: a = a0[p].z; break;
                    case 3: a = a0[p].w; break;
                    case 4: a = a1[p].x; break;
                    case 5: a = a1[p].y; break;
                    case 6: a = a1[p].z; break;
                    default: a = a1[p].w; break;
                }
                d[p][0] = fmaf(a, wd.x, d[p][0]);
                d[p][1] = fmaf(a, wd.y, d[p][1]);
                d[p][2] = fmaf(a, wd.z, d[p][2]);
            }
        }
    }
#pragma unroll
    for (int p = 0; p < 4; p++) {
        int gw = gbase + p;
        float d0 = d[p][0], d1 = d[p][1], d2 = d[p][2];
#pragma unroll
        for (int off = 16; off; off >>= 1) {
            d0 += __shfl_xor_sync(0xffffffffu, d0, off);
            d1 += __shfl_xor_sync(0xffffffffu, d1, off);
            d2 += __shfl_xor_sync(0xffffffffu, d2, off);
        }
        if (gw < NPIX && lane < 3) {
            float D = (lane == 0 ? d0 : (lane == 1 ? d1 : d2)) + s_bd[lane];
            float s = 1.f / (1.f + expf(-D));
            unsigned bits = __float_as_uint(s);
            unsigned key = bits ^ ((unsigned)((int)bits >> 31) | 0x80000000u);
            g_keys[gw * 3 + lane] = key;
            atomicAdd(&g_hist16[key >> 16], 1u);
        }
    }
}

// single block, 1024 threads, register-light: two streaming passes over g_hist16
__global__ void __launch_bounds__(1024) select16_kernel(int K) {
    __shared__ unsigned tot[1024];
    int t = threadIdx.x;
    int b0 = t * 64;
    unsigned sum = 0;
    for (int i = 0; i < 64; i++) sum += g_hist16[b0 + i];
    tot[t] = sum;
    __syncthreads();
    for (int d = 1; d < 1024; d <<= 1) {
        unsigned v = (t + d < 1024) ? tot[t + d] : 0u;
        __syncthreads();
        tot[t] += v;
        __syncthreads();
    }
    unsigned suffAfter = (t < 1023) ? tot[t + 1] : 0u;
    if (tot[t] >= (unsigned)K && suffAfter < (unsigned)K) {
        unsigned run = suffAfter;
        for (int i = 63; i >= 0; i--) {
            unsigned before = run;
            run += g_hist16[b0 + i];
            if (run >= (unsigned)K && before < (unsigned)K) {
                g_prefix = ((unsigned)(b0 + i)) << 16;
                break;
            }
        }
    }
}

// ---------------- pool marking + candidate list (order-free: rank is set-based) ----------------
__global__ void mark_compact_kernel() {
    unsigned T = g_prefix;
    for (int i = blockIdx.x * blockDim.x + threadIdx.x; i < NANCH;
         i += gridDim.x * blockDim.x) {
        if (g_keys[i] >= T) {    // approx keys at this stage
            int pix = i / 3;
            if (atomicExch(&g_pixFlag[pix], 1) == 0) {
                int p = atomicAdd(&g_poolCnt, 1);
                if (p < POOLMAX) g_poolPix[p] = pix;
            }
            int c = atomicAdd(&g_candCount, 1);
            if (c < CAND_MAX) g_candIdx[c] = i;
        }
    }
}

// ---------------- exact fp32 recompute of pool pixels (R1-identical chain, FFMA2) ----------------
// grid (256, 2), 256 threads. Tile: 32 pixels x 256 oc. Thread: 4 px x 8 oc (4 pairs).
__global__ void __launch_bounds__(256) exact_conv_kernel(const float* __restrict__ bias) {
    __shared__ float sA[32][33];
    __shared__ float sW[32][264];
    __shared__ int s_pix[32], s_base[32], s_W[32], s_H[32], s_py[32], s_px[32];

    const int tid = threadIdx.x;
    const int cnt = g_poolCnt < POOLMAX ? g_poolCnt : POOLMAX;
    const int ptile = blockIdx.x;
    if (ptile * 32 >= cnt) return;
    const int oc0 = blockIdx.y * 256;

    if (tid < 32) {
        int idx = ptile * 32 + tid;
        int pix = (idx < cnt) ? g_poolPix[idx] : -1;
        s_pix[tid] = pix;
        if (pix >= 0) {
            int l = 0;
            while (l < 4 && pix >= c_pixBase[l + 1]) l++;
            int local = pix - c_pixBase[l];
            int Wl = c_W[l];
            s_base[tid] = c_pixBase[l];
            s_W[tid] = Wl;
            s_H[tid] = c_H[l];
            s_py[tid] = local / Wl;
            s_px[tid] = local - (local / Wl) * Wl;
        }
    }
    __syncthreads();

    const int lane = tid & 31, wid = tid >> 5;
    const int ocL = wid * 32 + (lane >> 3) * 8;
    const int p0 = (lane & 7) * 4;

    const int ap = tid >> 3;
    const int akq = (tid & 7) * 4;
    const int wkk = tid >> 6;
    const int woc = (tid & 63) * 4;

    unsigned long long acc2[4][4];
#pragma unroll
    for (int i = 0; i < 4; i++)
#pragma unroll
        for (int j = 0; j < 4; j++) acc2[i][j] = 0ULL;

    for (int chunk = 0; chunk < 72; chunk++) {
        const int tap = chunk >> 3;
        const int ic0 = (chunk & 7) * 32;
        const int dy = tap / 3 - 1;
        const int dx = tap - (tap / 3) * 3 - 1;
        const int k0 = chunk * 32;
        {
            float4 val = make_float4(0.f, 0.f, 0.f, 0.f);
            int pix = s_pix[ap];
            if (pix >= 0) {
                int iy = s_py[ap] + dy, ix = s_px[ap] + dx;
                if ((unsigned)iy < (unsigned)s_H[ap] && (unsigned)ix < (unsigned)s_W[ap]) {
                    int np = s_base[ap] + iy * s_W[ap] + ix;
                    val = *(const float4*)(g_fp + (size_t)np * 256 + ic0 + akq);
                }
            }
            sA[ap][akq + 0] = val.x;
            sA[ap][akq + 1] = val.y;
            sA[ap][akq + 2] = val.z;
            sA[ap][akq + 3] = val.w;
        }
#pragma unroll
        for (int r = 0; r < 8; r++) {
            int kk = r * 4 + wkk;
            *(float4*)&sW[kk][woc] =
                *(const float4*)(g_wT + (size_t)(k0 + kk) * 512 + oc0 + woc);
        }
        __syncthreads();
#pragma unroll 8
        for (int kk = 0; kk < 32; kk++) {
            unsigned long long a0 = pack2(sA[p0 + 0][kk], sA[p0 + 0][kk]);
            unsigned long long a1 = pack2(sA[p0 + 1][kk], sA[p0 + 1][kk]);
            unsigned long long a2 = pack2(sA[p0 + 2][kk], sA[p0 + 2][kk]);
            unsigned long long a3 = pack2(sA[p0 + 3][kk], sA[p0 + 3][kk]);
#pragma unroll
            for (int jp = 0; jp < 4; jp++) {
                float2 wp = *(const float2*)&sW[kk][ocL + jp * 2];
                unsigned long long w2 = pack2(wp.x, wp.y);
                ffma2(acc2[0][jp], a0, w2);
                ffma2(acc2[1][jp], a1, w2);
                ffma2(acc2[2][jp], a2, w2);
                ffma2(acc2[3][jp], a3, w2);
            }
        }
        __syncthreads();
    }

#pragma unroll
    for (int i = 0; i < 4; i++) {
        int pix = s_pix[p0 + i];
        if (pix >= 0) {
            float* o = g_f + (size_t)pix * 512 + oc0 + ocL;
#pragma unroll
            for (int jp = 0; jp < 4; jp++) {
                float2 r = unpack2(acc2[i][jp]);
                o[jp * 2 + 0] = r.x + bias[oc0 + ocL + jp * 2 + 0];
                o[jp * 2 + 1] = r.y + bias[oc0 + ocL + jp * 2 + 1];
            }
        }
    }
}

// ---------------- exact heads on pool pixels (R1-identical, weights staged in smem) ----------------
__device__ __forceinline__ void heads_pixel(int gw, int lane,
        const float* __restrict__ sw, const float* __restrict__ sb,
        const float* __restrict__ bw, const float* __restrict__ bb)
{
    const float* f = g_f + (size_t)gw * 512;
    float4 v[4];
#pragma unroll
    for (int j = 0; j < 4; j++)
        v[j] = *(const float4*)(f + j * 128 + lane * 4);

    float c[6];
#pragma unroll
    for (int ch = 0; ch < 6; ch++) {
        const float* w = sw + ch * 512;
        float s = 0.f;
#pragma unroll
        for (int j = 0; j < 4; j++) {
            float4 ww = *(const float4*)(w + j * 128 + lane * 4);
            s += v[j].x * ww.x + v[j].y * ww.y + v[j].z * ww.z + v[j].w * ww.w;
        }
#pragma unroll
        for (int off = 16; off; off >>= 1) s += __shfl_xor_sync(0xffffffffu, s, off);
        c[ch] = s + sb[ch];
    }
    float d[12];
#pragma unroll
    for (int ch = 0; ch < 12; ch++) {
        const float* w = bw + ch * 512;
        float s = 0.f;
#pragma unroll
        for (int j = 0; j < 4; j++) {
            float4 ww = *(const float4*)(w + j * 128 + lane * 4);
            s += v[j].x * ww.x + v[j].y * ww.y + v[j].z * ww.z + v[j].w * ww.w;
        }
#pragma unroll
        for (int off = 16; off; off >>= 1) s += __shfl_xor_sync(0xffffffffu, s, off);
        d[ch] = s + bb[ch];
    }
    int base = gw * 3;
    if (lane < 3) {
        float s = 1.f / (1.f + expf(c[lane] - c[3 + lane]));
        unsigned bits = __float_as_uint(s);
        unsigned key = bits ^ ((unsigned)((int)bits >> 31) | 0x80000000u);
        g_keys[base + lane] = key;
    }
    if (lane < 12) {
        g_deltas[(size_t)base * 4 + lane] = d[lane];
    }
}

__global__ void __launch_bounds__(256) heads_pool_kernel(
        const float* __restrict__ sw, const float* __restrict__ sb,
        const float* __restrict__ bw, const float* __restrict__ bb)
{
    __shared__ __align__(16) float s_sw[6 * 512];
    __shared__ __align__(16) float s_bw[12 * 512];
    int tid = threadIdx.x;
    for (int i = tid; i < 6 * 512 / 4; i += 256)
        ((float4*)s_sw)[i] = ((const float4*)sw)[i];
    for (int i = tid; i < 12 * 512 / 4; i += 256)
        ((float4*)s_bw)[i] = ((const float4*)bw)[i];
    __syncthreads();
    int lane = tid & 31, wid = tid >> 5;
    int cnt = g_poolCnt < POOLMAX ? g_poolCnt : POOLMAX;
    for (int i = blockIdx.x * 8 + wid; i < cnt; i += gridDim.x * 8)
        heads_pixel(g_poolPix[i], lane, s_sw, sb, s_bw, bb);
}

// ---------------- compact: gather exact keys for the candidate list ----------------
__global__ void compact_kernel() {
    int t = blockIdx.x * blockDim.x + threadIdx.x;
    int cnt = g_candCount < CAND_MAX ? g_candCount : CAND_MAX;
    if (t >= cnt) {
        if (t < CAND_MAX) g_cand[t] = 0ULL;
        return;
    }
    int i = g_candIdx[t];
    g_cand[t] = ((unsigned long long)g_keys[i] << 32) | (unsigned)(~i);  // exact key
}

// ---------------- rank-and-scatter (replaces bitonic sort; identical order) ----------------
// rank(i) = #{j : cand_j > cand_i} with the same u64 comparator (key desc, idx asc).
#define RB 128
__global__ void __launch_bounds__(RB) rank_kernel(const float* __restrict__ im_info) {
    __shared__ unsigned long long sj[RB];
    int cnt = g_candCount < CAND_MAX ? g_candCount : CAND_MAX;
    int i = blockIdx.x * RB + threadIdx.x;
    unsigned long long mine = (i < cnt) ? g_cand[i] : 0ULL;
    int rank = 0;
    for (int j0 = 0; j0 < cnt; j0 += RB) {
        int j = j0 + threadIdx.x;
        sj[threadIdx.x] = (j < cnt) ? g_cand[j] : 0ULL;   // 0 never > valid cand
        __syncthreads();
#pragma unroll 8
        for (int jj = 0; jj < RB; jj++)
            rank += (sj[jj] > mine) ? 1 : 0;
        __syncthreads();
    }
    if (i >= cnt || rank >= PRE_NMS) return;
    unsigned long long e = mine;
    unsigned idxu = ~(unsigned)(e & 0xffffffffu);
    unsigned key = (unsigned)(e >> 32);
    unsigned bits = (key & 0x80000000u) ? (key ^ 0x80000000u) : ~key;
    g_selScore[rank] = __uint_as_float(bits);
    // ---- decode (identical arithmetic to prior decode) ----
    int id = (int)idxu;
    int l = 0;
    while (l < 4 && id >= c_aoff[l + 1]) l++;
    int local = id - c_aoff[l];
    int p = local / 3, a = local - p * 3;
    int W = c_W[l];
    int y = p / W, x = p - y * W;
    float stride = (float)c_stride[l];
    float cb = (stride - 1.f) * 0.5f;
    float ws = c_ws0[l * 3 + a] * 8.f, hs = c_hs0[l * 3 + a] * 8.f;
    float sx = x * stride, sy = y * stride;
    float ax1 = sx + cb - 0.5f * (ws - 1.f);
    float ay1 = sy + cb - 0.5f * (hs - 1.f);
    float ax2 = sx + cb + 0.5f * (ws - 1.f);
    float ay2 = sy + cb + 0.5f * (hs - 1.f);
    float w = ax2 - ax1 + 1.f, h = ay2 - ay1 + 1.f;
    float cx = ax1 + 0.5f * w, cy = ay1 + 0.5f * h;
    const float* dd = g_deltas + (size_t)id * 4;
    float pcx = dd[0] * w + cx;
    float pcy = dd[1] * h + cy;
    float pw = expf(dd[2]) * w;
    float ph = expf(dd[3]) * h;
    float imW = im_info[1] - 1.f, imH = im_info[0] - 1.f;
    g_boxes[rank * 4 + 0] = fminf(fmaxf(pcx - 0.5f * pw, 0.f), imW);
    g_boxes[rank * 4 + 1] = fminf(fmaxf(pcy - 0.5f * ph, 0.f), imH);
    g_boxes[rank * 4 + 2] = fminf(fmaxf(pcx + 0.5f * pw, 0.f), imW);
    g_boxes[rank * 4 + 3] = fminf(fmaxf(pcy + 0.5f * ph, 0.f), imH);
}

// ---------------- IoU suppression bitmask (smem-tiled) ----------------
__global__ void iou_kernel() {
    __shared__ float4 sj[64];
    int wb = blockIdx.y;
    int t = threadIdx.x;
    int j0 = wb * 64;
    {
        int j = j0 + t;
        sj[t] = (j < PRE_NMS) ? ((const float4*)g_boxes)[j]
                              : make_float4(0.f, 0.f, 0.f, 0.f);
    }
    __syncthreads();
    int i = blockIdx.x * 64 + t;
    if (i >= PRE_NMS) return;
    float4 bi = ((const float4*)g_boxes)[i];
    float areaI = (bi.z - bi.x + 1.f) * (bi.w - bi.y + 1.f);
    unsigned long long m = 0;
    int jend = PRE_NMS - j0; if (jend > 64) jend = 64;
    for (int jj = 0; jj < jend; jj++) {
        float4 bj = sj[jj];
        float areaJ = (bj.z - bj.x + 1.f) * (bj.w - bj.y + 1.f);
        float iw = fminf(bi.z, bj.z) - fmaxf(bi.x, bj.x) + 1.f;
        float ih = fminf(bi.w, bj.w) - fmaxf(bi.y, bj.y) + 1.f;
        iw = fmaxf(iw, 0.f); ih = fmaxf(ih, 0.f);
        float inter = iw * ih;
        float iou = inter / (areaJ + areaI - inter);
        if (iou > NMS_TH) m |= (1ULL << jj);
    }
    g_iou[(size_t)i * NWORDS + wb] = m;
}

// ---------------- single-warp greedy NMS with 16-way row prefetch ----------------
__global__ void nms_kernel() {
    int lane = threadIdx.x;
    unsigned long long rem0 = 0, rem1 = 0, rem2 = 0;
    int w2 = lane + 64;
    if (w2 == 93) rem2 = ~((1ULL << 48) - 1ULL);
    else if (w2 > 93) rem2 = ~0ULL;
    int nk = 0;
    while (nk < POST_NMS) {
        unsigned long long a0 = ~rem0, a1 = ~rem1, a2 = ~rem2;
        int cand[16];
#pragma unroll
        for (int t = 0; t < 16; t++) cand[t] = -1;
#pragma unroll
        for (int t = 0; t < 16; t++) {
            unsigned b0 = __ballot_sync(0xffffffffu, a0 != 0ULL);
            unsigned b1 = __ballot_sync(0xffffffffu, a1 != 0ULL);
            unsigned b2 = __ballot_sync(0xffffffffu, a2 != 0ULL);
            int slot = -1, src = 0;
            if (b0) { slot = 0; src = __ffs(b0) - 1; }
            else if (b1) { slot = 1; src = __ffs(b1) - 1; }
            else if (b2) { slot = 2; src = __ffs(b2) - 1; }
            if (slot < 0) break;
            unsigned long long mysel = (slot == 0) ? a0 : ((slot == 1) ? a1 : a2);
            int mybit = __ffsll((long long)mysel) - 1;
            int bit = __shfl_sync(0xffffffffu, mybit, src);
            cand[t] = (slot * 32 + src) * 64 + bit;
            if (lane == src) {
                if (slot == 0) a0 &= (a0 - 1);
                else if (slot == 1) a1 &= (a1 - 1);
                else a2 &= (a2 - 1);
            }
        }
        if (cand[0] < 0) break;
        unsigned long long r[16][3];
#pragma unroll
        for (int t = 0; t < 16; t++) {
            if (cand[t] >= 0) {
                const unsigned long long* row = g_iou + (size_t)cand[t] * NWORDS;
                r[t][0] = __ldg(row + lane);
                r[t][1] = __ldg(row + lane + 32);
                r[t][2] = (w2 < NWORDS) ? __ldg(row + w2) : 0ULL;
            } else {
                r[t][0] = r[t][1] = r[t][2] = 0ULL;
            }
        }
#pragma unroll
        for (int t = 0; t < 16; t++) {
            int idx = cand[t];
            if (idx < 0 || nk >= POST_NMS) break;
            if (t > 0) {
                int w = idx >> 6, b = idx & 63;
                unsigned long long mine = (w < 32) ? rem0 : ((w < 64) ? rem1 : rem2);
                unsigned long long ow = __shfl_sync(0xffffffffu, mine, w & 31);
                if ((ow >> b) & 1ULL) continue;
            }
            if (lane == 0) g_keep[nk] = idx;
            nk++;
            rem0 |= r[t][0]; rem1 |= r[t][1]; rem2 |= r[t][2];
        }
    }
    if (lane == 0) g_numKeep = nk;
}

// ---------------- assemble output (1000 x 6) ----------------
__global__ void output_kernel(float* __restrict__ out) {
    int i = blockIdx.x * blockDim.x + threadIdx.x;
    if (i >= POST_NMS) return;
    float x1 = 0, y1 = 0, x2 = 0, y2 = 0, s = 0;
    int nk = g_numKeep;
    if (i < nk) {
        int k = g_keep[i];
        x1 = g_boxes[k * 4 + 0]; y1 = g_boxes[k * 4 + 1];
        x2 = g_boxes[k * 4 + 2]; y2 = g_boxes[k * 4 + 3];
        s = g_selScore[k];
    }
    out[i * 6 + 0] = 0.f;
    out[i * 6 + 1] = x1;
    out[i * 6 + 2] = y1;
    out[i * 6 + 3] = x2;
    out[i * 6 + 4] = y2;
    out[i * 6 + 5] = s;
}

// ---------------- launch ----------------
extern "C" void kernel_launch(void* const* d_in, const int* in_sizes, int n_in,
                              void* d_out, int out_size) {
    const float* feats[5];
    for (int i = 0; i < 5; i++) feats[i] = (const float*)d_in[i];
    const float* im_info = (const float*)d_in[5];
    const float* convW = (const float*)d_in[6];
    const float* convB = (const float*)d_in[7];
    const float* sw = (const float*)d_in[8];
    const float* sb = (const float*)d_in[9];
    const float* bw = (const float*)d_in[10];
    const float* bb = (const float*)d_in[11];
    float* out = (float*)d_out;

    prep_kernel<<<dim3(1109, 8), dim3(32, 32)>>>(feats[0], feats[1], feats[2],
                                                 feats[3], feats[4]);
    repackw_kernel<<<(512 * 2304 + 255) / 256, 256>>>(convW);
    fold_kernel<<<(2304 * 3 + 255) / 256, 256>>>(sw, sb, convB);
    approx_score_kernel<<<1109, 256>>>();
    select16_kernel<<<1, 1024>>>(POOL_K);
    mark_compact_kernel<<<416, 256>>>();
    exact_conv_kernel<<<dim3(256, 2), 256>>>(convB);
    heads_pool_kernel<<<128, 256>>>(sw, sb, bw, bb);
    compact_kernel<<<CAND_MAX / 256, 256>>>();
    rank_kernel<<<CAND_MAX / RB, RB>>>(im_info);
    iou_kernel<<<dim3(94, 94), 64>>>();
    nms_kernel<<<1, 32>>>();
    output_kernel<<<(POST_NMS + 255) / 256, 256>>>(out);
}

// round 17
// speedup vs baseline: 1.2374x; 1.0276x over previous
#include <cuda_runtime.h>
#include <math.h>
#include <stdint.h>

#define NPIX 35464
#define NANCH 106392
#define PRE_NMS 6000
#define POOL_K 6656
#define POOLMAX 8192
#define POST_NMS 1000
#define NMS_TH 0.7f
#define CAND_MAX 8192
#define NWORDS 94    // ceil(6000/64)

// ---------------- device scratch ----------------
__device__ float g_f[(size_t)NPIX * 512];     // exact features (pool pixels only)
__device__ float g_fp[(size_t)NPIX * 256];    // fp32 input, pixel-major
__device__ float g_wT[2304 * 512];            // fp32 conv weights [k][oc]
__device__ float g_wd[2304 * 3];              // folded diff weights [k][a]
__device__ float g_wdB[3];                    // folded diff bias
__device__ unsigned g_keys[NANCH];            // approx, then exact for pool anchors
__device__ float g_deltas[(size_t)NANCH * 4];
__device__ unsigned g_hist16[65536];
__device__ unsigned g_prefix;
__device__ int g_candCount;
__device__ int g_candIdx[CAND_MAX];
__device__ unsigned long long g_cand[CAND_MAX];
__device__ int g_pixFlag[NPIX];
__device__ int g_poolPix[POOLMAX];
__device__ int g_poolCnt;
__device__ float g_selScore[PRE_NMS];
__device__ float g_boxes[PRE_NMS * 4];
__device__ unsigned long long g_iou[(size_t)PRE_NMS * NWORDS];
__device__ int g_keep[POST_NMS];
__device__ int g_numKeep;

// constants
__constant__ int c_aoff[6] = {0, 79872, 99840, 104832, 106080, 106392};
__constant__ int c_W[5] = {208, 104, 52, 26, 13};
__constant__ int c_H[5] = {128, 64, 32, 16, 8};
__constant__ int c_stride[5] = {4, 8, 16, 32, 64};
__constant__ int c_pixBase[5] = {0, 26624, 33280, 34944, 35360};
__constant__ int c_ws0[15] = {6,4,3, 11,8,6, 23,16,11, 45,32,23, 91,64,45};
__constant__ int c_hs0[15] = {3,4,6, 6,8,12, 12,16,22, 22,32,46, 46,64,90};

// ---------------- f32x2 helpers (per-component == fma.rn.f32, bit-exact) ----------------
__device__ __forceinline__ void ffma2(unsigned long long& c, unsigned long long a,
                                      unsigned long long b) {
    asm("fma.rn.f32x2 %0, %1, %2, %3;" : "=l"(c) : "l"(a), "l"(b), "l"(c));
}
__device__ __forceinline__ unsigned long long pack2(float x, float y) {
    unsigned long long r;
    asm("mov.b64 %0, {%1, %2};" : "=l"(r) : "f"(x), "f"(y));
    return r;
}
__device__ __forceinline__ float2 unpack2(unsigned long long v) {
    float2 r;
    asm("mov.b64 {%0, %1}, %2;" : "=f"(r.x), "=f"(r.y) : "l"(v));
    return r;
}

// ---------------- prep (all 5 levels fused): NCHW fp32 -> pixel-major fp32 ----------------
__global__ void prep_kernel(const float* __restrict__ p2, const float* __restrict__ p3,
                            const float* __restrict__ p4, const float* __restrict__ p5,
                            const float* __restrict__ p6) {
    __shared__ float sh[32][33];
    int g0 = blockIdx.x * 32;
    int l = 0;
    while (l < 4 && g0 >= c_pixBase[l + 1]) l++;
    const float* f = (l == 0) ? p2 : (l == 1) ? p3 : (l == 2) ? p4 : (l == 3) ? p5 : p6;
    int HW = c_W[l] * c_H[l];
    int base = c_pixBase[l];
    int ic0 = blockIdx.y * 32;
    int tx = threadIdx.x, ty = threadIdx.y;
    int p = g0 - base + tx;
    sh[ty][tx] = (p < HW) ? f[(size_t)(ic0 + ty) * HW + p] : 0.f;
    __syncthreads();
    int pw = g0 - base + ty;
    if (pw < HW)
        g_fp[(size_t)(base + pw) * 256 + ic0 + tx] = sh[tx][ty];
}

// ---------------- weight transpose + zero scratch ----------------
__global__ void repackw_kernel(const float* __restrict__ w) {
    int t = blockIdx.x * blockDim.x + threadIdx.x;
    if (t < 65536) g_hist16[t] = 0;
    if (t < NPIX) g_pixFlag[t] = 0;
    if (t == 0) { g_candCount = 0; g_numKeep = 0; g_poolCnt = 0; }
    if (t >= 512 * 2304) return;
    int oc = t / 2304, k = t - oc * 2304;
    int tap = k >> 8, ic = k & 255;
    g_wT[k * 512 + oc] = w[oc * 2304 + ic * 9 + tap];
}

// ---------------- fold score-diff head into conv: wd[k][a] = Weff[k][3+a]-Weff[k][a] ----------------
__global__ void fold_kernel(const float* __restrict__ sw, const float* __restrict__ sb,
                            const float* __restrict__ convB) {
    int t = blockIdx.x * blockDim.x + threadIdx.x;
    if (t < 3) {
        float acc = sb[3 + t] - sb[t];
        for (int oc = 0; oc < 512; oc++)
            acc += (sw[(3 + t) * 512 + oc] - sw[t * 512 + oc]) * convB[oc];
        g_wdB[t] = acc;
    }
    if (t >= 2304 * 3) return;
    int k = t / 3, a = t - k * 3;
    const float4* wr = (const float4*)(g_wT + (size_t)k * 512);
    const float4* s0 = (const float4*)(sw + a * 512);
    const float4* s1 = (const float4*)(sw + (3 + a) * 512);
    float acc = 0.f;
#pragma unroll 4
    for (int q = 0; q < 128; q++) {
        float4 wv = wr[q];
        float4 b0 = s0[q], b1 = s1[q];
        acc += wv.x * (b1.x - b0.x) + wv.y * (b1.y - b0.y)
             + wv.z * (b1.z - b0.z) + wv.w * (b1.w - b0.w);
    }
    g_wd[t] = acc;
}

// ---------------- approx scores + fused histogram ----------------
__global__ void __launch_bounds__(256) approx_score_kernel() {
    __shared__ float s_wd[2304 * 4 + 288 * 4];   // 41472 B
    __shared__ float s_bd[3];
    int tid = threadIdx.x;
    for (int k = tid; k < 2304; k += 256) {
        int base = k * 4 + (k >> 3) * 4;
        s_wd[base + 0] = g_wd[k * 3 + 0];
        s_wd[base + 1] = g_wd[k * 3 + 1];
        s_wd[base + 2] = g_wd[k * 3 + 2];
        s_wd[base + 3] = 0.f;
    }
    if (tid < 3) s_bd[tid] = g_wdB[tid];
    __syncthreads();
    int lane = tid & 31;
    const int ic0 = lane * 8;
    const int gbase = blockIdx.x * 32 + (tid >> 5) * 4;

    int pb[4], pW[4], pH[4], ppy[4], ppx[4];
#pragma unroll
    for (int p = 0; p < 4; p++) {
        int gw = gbase + p;
        if (gw < NPIX) {
            int l = 0;
            while (l < 4 && gw >= c_pixBase[l + 1]) l++;
            int Wl = c_W[l];
            int local = gw - c_pixBase[l];
            pb[p] = c_pixBase[l];
            pW[p] = Wl;
            pH[p] = c_H[l];
            ppy[p] = local / Wl;
            ppx[p] = local - (local / Wl) * Wl;
        } else {
            pb[p] = 0; pW[p] = 1; pH[p] = -1; ppy[p] = -100; ppx[p] = -100;
        }
    }
    float d[4][3];
#pragma unroll
    for (int p = 0; p < 4; p++) d[p][0] = d[p][1] = d[p][2] = 0.f;

#pragma unroll
    for (int tap = 0; tap < 9; tap++) {
        int dy = tap / 3 - 1, dx = tap % 3 - 1;
        float4 a0[4], a1[4];
#pragma unroll
        for (int p = 0; p < 4; p++) {
            int iy = ppy[p] + dy, ix = ppx[p] + dx;
            if ((unsigned)iy < (unsigned)pH[p] && (unsigned)ix < (unsigned)pW[p]) {
                const float* src = g_fp + ((size_t)(pb[p] + iy * pW[p] + ix)) * 256 + ic0;
                a0[p] = *(const float4*)src;
                a1[p] = *(const float4*)(src + 4);
            } else {
                a0[p] = make_float4(0.f, 0.f, 0.f, 0.f);
                a1[p] = a0[p];
            }
        }
        const float* wp = s_wd + tap * 1152 + lane * 36;
#pragma unroll
        for (int j = 0; j < 8; j++) {
            float4 wd = *(const float4*)(wp + j * 4);
#pragma unroll
            for (int p = 0; p < 4; p++) {
                float a;
                switch (j) {
                    case 0: a = a0[p].x; break;
                    case 1: a = a0[p].y; break;
                    case 2: a = a0[p].z; break;
                    case 3: a = a0[p].w; break;
                    case 4: a = a1[p].x; break;
                    case 5: a = a1[p].y; break;
                    case 6: a = a1[p].z; break;
                    default: a = a1[p].w; break;
                }
                d[p][0] = fmaf(a, wd.x, d[p][0]);
                d[p][1] = fmaf(a, wd.y, d[p][1]);
                d[p][2] = fmaf(a, wd.z, d[p][2]);
            }
        }
    }
#pragma unroll
    for (int p = 0; p < 4; p++) {
        int gw = gbase + p;
        float d0 = d[p][0], d1 = d[p][1], d2 = d[p][2];
#pragma unroll
        for (int off = 16; off; off >>= 1) {
            d0 += __shfl_xor_sync(0xffffffffu, d0, off);
            d1 += __shfl_xor_sync(0xffffffffu, d1, off);
            d2 += __shfl_xor_sync(0xffffffffu, d2, off);
        }
        if (gw < NPIX && lane < 3) {
            float D = (lane == 0 ? d0 : (lane == 1 ? d1 : d2)) + s_bd[lane];
            float s = 1.f / (1.f + expf(-D));
            unsigned bits = __float_as_uint(s);
            unsigned key = bits ^ ((unsigned)((int)bits >> 31) | 0x80000000u);
            g_keys[gw * 3 + lane] = key;
            atomicAdd(&g_hist16[key >> 16], 1u);
        }
    }
}

// single block, 1024 threads, register-light: two streaming passes over g_hist16
__global__ void __launch_bounds__(1024) select16_kernel(int K) {
    __shared__ unsigned tot[1024];
    int t = threadIdx.x;
    int b0 = t * 64;
    unsigned sum = 0;
    for (int i = 0; i < 64; i++) sum += g_hist16[b0 + i];
    tot[t] = sum;
    __syncthreads();
    for (int d = 1; d < 1024; d <<= 1) {
        unsigned v = (t + d < 1024) ? tot[t + d] : 0u;
        __syncthreads();
        tot[t] += v;
        __syncthreads();
    }
    unsigned suffAfter = (t < 1023) ? tot[t + 1] : 0u;
    if (tot[t] >= (unsigned)K && suffAfter < (unsigned)K) {
        unsigned run = suffAfter;
        for (int i = 63; i >= 0; i--) {
            unsigned before = run;
            run += g_hist16[b0 + i];
            if (run >= (unsigned)K && before < (unsigned)K) {
                g_prefix = ((unsigned)(b0 + i)) << 16;
                break;
            }
        }
    }
}

// ---------------- pool marking + candidate list (order-free: rank is set-based) ----------------
__global__ void mark_compact_kernel() {
    unsigned T = g_prefix;
    for (int i = blockIdx.x * blockDim.x + threadIdx.x; i < NANCH;
         i += gridDim.x * blockDim.x) {
        if (g_keys[i] >= T) {    // approx keys at this stage
            int pix = i / 3;
            if (atomicExch(&g_pixFlag[pix], 1) == 0) {
                int p = atomicAdd(&g_poolCnt, 1);
                if (p < POOLMAX) g_poolPix[p] = pix;
            }
            int c = atomicAdd(&g_candCount, 1);
            if (c < CAND_MAX) g_candIdx[c] = i;
        }
    }
}

// ---------------- exact fp32 recompute of pool pixels (R1-identical chain, FFMA2) ----------------
__global__ void __launch_bounds__(256) exact_conv_kernel(const float* __restrict__ bias) {
    __shared__ float sA[32][33];
    __shared__ float sW[32][264];
    __shared__ int s_pix[32], s_base[32], s_W[32], s_H[32], s_py[32], s_px[32];

    const int tid = threadIdx.x;
    const int cnt = g_poolCnt < POOLMAX ? g_poolCnt : POOLMAX;
    const int ptile = blockIdx.x;
    if (ptile * 32 >= cnt) return;
    const int oc0 = blockIdx.y * 256;

    if (tid < 32) {
        int idx = ptile * 32 + tid;
        int pix = (idx < cnt) ? g_poolPix[idx] : -1;
        s_pix[tid] = pix;
        if (pix >= 0) {
            int l = 0;
            while (l < 4 && pix >= c_pixBase[l + 1]) l++;
            int local = pix - c_pixBase[l];
            int Wl = c_W[l];
            s_base[tid] = c_pixBase[l];
            s_W[tid] = Wl;
            s_H[tid] = c_H[l];
            s_py[tid] = local / Wl;
            s_px[tid] = local - (local / Wl) * Wl;
        }
    }
    __syncthreads();

    const int lane = tid & 31, wid = tid >> 5;
    const int ocL = wid * 32 + (lane >> 3) * 8;
    const int p0 = (lane & 7) * 4;

    const int ap = tid >> 3;
    const int akq = (tid & 7) * 4;
    const int wkk = tid >> 6;
    const int woc = (tid & 63) * 4;

    unsigned long long acc2[4][4];
#pragma unroll
    for (int i = 0; i < 4; i++)
#pragma unroll
        for (int j = 0; j < 4; j++) acc2[i][j] = 0ULL;

    for (int chunk = 0; chunk < 72; chunk++) {
        const int tap = chunk >> 3;
        const int ic0 = (chunk & 7) * 32;
        const int dy = tap / 3 - 1;
        const int dx = tap - (tap / 3) * 3 - 1;
        const int k0 = chunk * 32;
        {
            float4 val = make_float4(0.f, 0.f, 0.f, 0.f);
            int pix = s_pix[ap];
            if (pix >= 0) {
                int iy = s_py[ap] + dy, ix = s_px[ap] + dx;
                if ((unsigned)iy < (unsigned)s_H[ap] && (unsigned)ix < (unsigned)s_W[ap]) {
                    int np = s_base[ap] + iy * s_W[ap] + ix;
                    val = *(const float4*)(g_fp + (size_t)np * 256 + ic0 + akq);
                }
            }
            sA[ap][akq + 0] = val.x;
            sA[ap][akq + 1] = val.y;
            sA[ap][akq + 2] = val.z;
            sA[ap][akq + 3] = val.w;
        }
#pragma unroll
        for (int r = 0; r < 8; r++) {
            int kk = r * 4 + wkk;
            *(float4*)&sW[kk][woc] =
                *(const float4*)(g_wT + (size_t)(k0 + kk) * 512 + oc0 + woc);
        }
        __syncthreads();
#pragma unroll 8
        for (int kk = 0; kk < 32; kk++) {
            unsigned long long a0 = pack2(sA[p0 + 0][kk], sA[p0 + 0][kk]);
            unsigned long long a1 = pack2(sA[p0 + 1][kk], sA[p0 + 1][kk]);
            unsigned long long a2 = pack2(sA[p0 + 2][kk], sA[p0 + 2][kk]);
            unsigned long long a3 = pack2(sA[p0 + 3][kk], sA[p0 + 3][kk]);
#pragma unroll
            for (int jp = 0; jp < 4; jp++) {
                float2 wp = *(const float2*)&sW[kk][ocL + jp * 2];
                unsigned long long w2 = pack2(wp.x, wp.y);
                ffma2(acc2[0][jp], a0, w2);
                ffma2(acc2[1][jp], a1, w2);
                ffma2(acc2[2][jp], a2, w2);
                ffma2(acc2[3][jp], a3, w2);
            }
        }
        __syncthreads();
    }

#pragma unroll
    for (int i = 0; i < 4; i++) {
        int pix = s_pix[p0 + i];
        if (pix >= 0) {
            float* o = g_f + (size_t)pix * 512 + oc0 + ocL;
#pragma unroll
            for (int jp = 0; jp < 4; jp++) {
                float2 r = unpack2(acc2[i][jp]);
                o[jp * 2 + 0] = r.x + bias[oc0 + ocL + jp * 2 + 0];
                o[jp * 2 + 1] = r.y + bias[oc0 + ocL + jp * 2 + 1];
            }
        }
    }
}

// ---------------- exact heads on pool pixels (R1-identical, weights staged in smem) ----------------
__device__ __forceinline__ void heads_pixel(int gw, int lane,
        const float* __restrict__ sw, const float* __restrict__ sb,
        const float* __restrict__ bw, const float* __restrict__ bb)
{
    const float* f = g_f + (size_t)gw * 512;
    float4 v[4];
#pragma unroll
    for (int j = 0; j < 4; j++)
        v[j] = *(const float4*)(f + j * 128 + lane * 4);

    float c[6];
#pragma unroll
    for (int ch = 0; ch < 6; ch++) {
        const float* w = sw + ch * 512;
        float s = 0.f;
#pragma unroll
        for (int j = 0; j < 4; j++) {
            float4 ww = *(const float4*)(w + j * 128 + lane * 4);
            s += v[j].x * ww.x + v[j].y * ww.y + v[j].z * ww.z + v[j].w * ww.w;
        }
#pragma unroll
        for (int off = 16; off; off >>= 1) s += __shfl_xor_sync(0xffffffffu, s, off);
        c[ch] = s + sb[ch];
    }
    float d[12];
#pragma unroll
    for (int ch = 0; ch < 12; ch++) {
        const float* w = bw + ch * 512;
        float s = 0.f;
#pragma unroll
        for (int j = 0; j < 4; j++) {
            float4 ww = *(const float4*)(w + j * 128 + lane * 4);
            s += v[j].x * ww.x + v[j].y * ww.y + v[j].z * ww.z + v[j].w * ww.w;
        }
#pragma unroll
        for (int off = 16; off; off >>= 1) s += __shfl_xor_sync(0xffffffffu, s, off);
        d[ch] = s + bb[ch];
    }
    int base = gw * 3;
    if (lane < 3) {
        float s = 1.f / (1.f + expf(c[lane] - c[3 + lane]));
        unsigned bits = __float_as_uint(s);
        unsigned key = bits ^ ((unsigned)((int)bits >> 31) | 0x80000000u);
        g_keys[base + lane] = key;
    }
    if (lane < 12) {
        g_deltas[(size_t)base * 4 + lane] = d[lane];
    }
}

__global__ void __launch_bounds__(256) heads_pool_kernel(
        const float* __restrict__ sw, const float* __restrict__ sb,
        const float* __restrict__ bw, const float* __restrict__ bb)
{
    __shared__ __align__(16) float s_sw[6 * 512];
    __shared__ __align__(16) float s_bw[12 * 512];
    int tid = threadIdx.x;
    for (int i = tid; i < 6 * 512 / 4; i += 256)
        ((float4*)s_sw)[i] = ((const float4*)sw)[i];
    for (int i = tid; i < 12 * 512 / 4; i += 256)
        ((float4*)s_bw)[i] = ((const float4*)bw)[i];
    __syncthreads();
    int lane = tid & 31, wid = tid >> 5;
    int cnt = g_poolCnt < POOLMAX ? g_poolCnt : POOLMAX;
    for (int i = blockIdx.x * 8 + wid; i < cnt; i += gridDim.x * 8)
        heads_pixel(g_poolPix[i], lane, s_sw, sb, s_bw, bb);
}

// ---------------- compact: gather exact keys for the candidate list ----------------
__global__ void compact_kernel() {
    int t = blockIdx.x * blockDim.x + threadIdx.x;
    int cnt = g_candCount < CAND_MAX ? g_candCount : CAND_MAX;
    if (t >= cnt) {
        if (t < CAND_MAX) g_cand[t] = 0ULL;
        return;
    }
    int i = g_candIdx[t];
    g_cand[t] = ((unsigned long long)g_keys[i] << 32) | (unsigned)(~i);  // exact key
}

// ---------------- rank-and-scatter (identical order to full sort) ----------------
#define RB 128
__global__ void __launch_bounds__(RB) rank_kernel(const float* __restrict__ im_info) {
    __shared__ unsigned long long sj[RB];
    int cnt = g_candCount < CAND_MAX ? g_candCount : CAND_MAX;
    int i = blockIdx.x * RB + threadIdx.x;
    unsigned long long mine = (i < cnt) ? g_cand[i] : 0ULL;
    int rank = 0;
    for (int j0 = 0; j0 < cnt; j0 += RB) {
        int j = j0 + threadIdx.x;
        sj[threadIdx.x] = (j < cnt) ? g_cand[j] : 0ULL;
        __syncthreads();
#pragma unroll 8
        for (int jj = 0; jj < RB; jj++)
            rank += (sj[jj] > mine) ? 1 : 0;
        __syncthreads();
    }
    if (i >= cnt || rank >= PRE_NMS) return;
    unsigned long long e = mine;
    unsigned idxu = ~(unsigned)(e & 0xffffffffu);
    unsigned key = (unsigned)(e >> 32);
    unsigned bits = (key & 0x80000000u) ? (key ^ 0x80000000u) : ~key;
    g_selScore[rank] = __uint_as_float(bits);
    int id = (int)idxu;
    int l = 0;
    while (l < 4 && id >= c_aoff[l + 1]) l++;
    int local = id - c_aoff[l];
    int p = local / 3, a = local - p * 3;
    int W = c_W[l];
    int y = p / W, x = p - y * W;
    float stride = (float)c_stride[l];
    float cb = (stride - 1.f) * 0.5f;
    float ws = c_ws0[l * 3 + a] * 8.f, hs = c_hs0[l * 3 + a] * 8.f;
    float sx = x * stride, sy = y * stride;
    float ax1 = sx + cb - 0.5f * (ws - 1.f);
    float ay1 = sy + cb - 0.5f * (hs - 1.f);
    float ax2 = sx + cb + 0.5f * (ws - 1.f);
    float ay2 = sy + cb + 0.5f * (hs - 1.f);
    float w = ax2 - ax1 + 1.f, h = ay2 - ay1 + 1.f;
    float cx = ax1 + 0.5f * w, cy = ay1 + 0.5f * h;
    const float* dd = g_deltas + (size_t)id * 4;
    float pcx = dd[0] * w + cx;
    float pcy = dd[1] * h + cy;
    float pw = expf(dd[2]) * w;
    float ph = expf(dd[3]) * h;
    float imW = im_info[1] - 1.f, imH = im_info[0] - 1.f;
    g_boxes[rank * 4 + 0] = fminf(fmaxf(pcx - 0.5f * pw, 0.f), imW);
    g_boxes[rank * 4 + 1] = fminf(fmaxf(pcy - 0.5f * ph, 0.f), imH);
    g_boxes[rank * 4 + 2] = fminf(fmaxf(pcx + 0.5f * pw, 0.f), imW);
    g_boxes[rank * 4 + 3] = fminf(fmaxf(pcy + 0.5f * ph, 0.f), imH);
}

// ---------------- IoU suppression bitmask (triangular: only j >= i needed) ----------------
__global__ void iou_kernel() {
    __shared__ float4 sj[64];
    int wb = blockIdx.y;
    int t = threadIdx.x;
    int j0 = wb * 64;
    int iBase = blockIdx.x * 64;
    // whole block strictly below diagonal: rows i in [iBase, iBase+64) all have j-range < i
    if (j0 + 64 <= iBase) {
        int i = iBase + t;
        if (i < PRE_NMS) g_iou[(size_t)i * NWORDS + wb] = 0ULL;
        return;
    }
    {
        int j = j0 + t;
        sj[t] = (j < PRE_NMS) ? ((const float4*)g_boxes)[j]
                              : make_float4(0.f, 0.f, 0.f, 0.f);
    }
    __syncthreads();
    int i = iBase + t;
    if (i >= PRE_NMS) return;
    float4 bi = ((const float4*)g_boxes)[i];
    float areaI = (bi.z - bi.x + 1.f) * (bi.w - bi.y + 1.f);
    unsigned long long m = 0;
    int jend = PRE_NMS - j0; if (jend > 64) jend = 64;
    for (int jj = 0; jj < jend; jj++) {
        if (j0 + jj < i) continue;   // j < i never consulted by greedy scan
        float4 bj = sj[jj];
        float areaJ = (bj.z - bj.x + 1.f) * (bj.w - bj.y + 1.f);
        float iw = fminf(bi.z, bj.z) - fmaxf(bi.x, bj.x) + 1.f;
        float ih = fminf(bi.w, bj.w) - fmaxf(bi.y, bj.y) + 1.f;
        iw = fmaxf(iw, 0.f); ih = fmaxf(ih, 0.f);
        float inter = iw * ih;
        float iou = inter / (areaJ + areaI - inter);
        if (iou > NMS_TH) m |= (1ULL << jj);
    }
    g_iou[(size_t)i * NWORDS + wb] = m;
}

// ---------------- single-warp greedy NMS with 16-way row prefetch ----------------
__global__ void nms_kernel() {
    int lane = threadIdx.x;
    unsigned long long rem0 = 0, rem1 = 0, rem2 = 0;
    int w2 = lane + 64;
    if (w2 == 93) rem2 = ~((1ULL << 48) - 1ULL);
    else if (w2 > 93) rem2 = ~0ULL;
    int nk = 0;
    while (nk < POST_NMS) {
        unsigned long long a0 = ~rem0, a1 = ~rem1, a2 = ~rem2;
        int cand[16];
#pragma unroll
        for (int t = 0; t < 16; t++) cand[t] = -1;
#pragma unroll
        for (int t = 0; t < 16; t++) {
            unsigned b0 = __ballot_sync(0xffffffffu, a0 != 0ULL);
            unsigned b1 = __ballot_sync(0xffffffffu, a1 != 0ULL);
            unsigned b2 = __ballot_sync(0xffffffffu, a2 != 0ULL);
            int slot = -1, src = 0;
            if (b0) { slot = 0; src = __ffs(b0) - 1; }
            else if (b1) { slot = 1; src = __ffs(b1) - 1; }
            else if (b2) { slot = 2; src = __ffs(b2) - 1; }
            if (slot < 0) break;
            unsigned long long mysel = (slot == 0) ? a0 : ((slot == 1) ? a1 : a2);
            int mybit = __ffsll((long long)mysel) - 1;
            int bit = __shfl_sync(0xffffffffu, mybit, src);
            cand[t] = (slot * 32 + src) * 64 + bit;
            if (lane == src) {
                if (slot == 0) a0 &= (a0 - 1);
                else if (slot == 1) a1 &= (a1 - 1);
                else a2 &= (a2 - 1);
            }
        }
        if (cand[0] < 0) break;
        unsigned long long r[16][3];
#pragma unroll
        for (int t = 0; t < 16; t++) {
            if (cand[t] >= 0) {
                const unsigned long long* row = g_iou + (size_t)cand[t] * NWORDS;
                r[t][0] = __ldg(row + lane);
                r[t][1] = __ldg(row + lane + 32);
                r[t][2] = (w2 < NWORDS) ? __ldg(row + w2) : 0ULL;
            } else {
                r[t][0] = r[t][1] = r[t][2] = 0ULL;
            }
        }
#pragma unroll
        for (int t = 0; t < 16; t++) {
            int idx = cand[t];
            if (idx < 0 || nk >= POST_NMS) break;
            if (t > 0) {
                int w = idx >> 6, b = idx & 63;
                unsigned long long mine = (w < 32) ? rem0 : ((w < 64) ? rem1 : rem2);
                unsigned long long ow = __shfl_sync(0xffffffffu, mine, w & 31);
                if ((ow >> b) & 1ULL) continue;
            }
            if (lane == 0) g_keep[nk] = idx;
            nk++;
            rem0 |= r[t][0]; rem1 |= r[t][1]; rem2 |= r[t][2];
        }
    }
    if (lane == 0) g_numKeep = nk;
}

// ---------------- assemble output (1000 x 6) ----------------
__global__ void output_kernel(float* __restrict__ out) {
    int i = blockIdx.x * blockDim.x + threadIdx.x;
    if (i >= POST_NMS) return;
    float x1 = 0, y1 = 0, x2 = 0, y2 = 0, s = 0;
    int nk = g_numKeep;
    if (i < nk) {
        int k = g_keep[i];
        x1 = g_boxes[k * 4 + 0]; y1 = g_boxes[k * 4 + 1];
        x2 = g_boxes[k * 4 + 2]; y2 = g_boxes[k * 4 + 3];
        s = g_selScore[k];
    }
    out[i * 6 + 0] = 0.f;
    out[i * 6 + 1] = x1;
    out[i * 6 + 2] = y1;
    out[i * 6 + 3] = x2;
    out[i * 6 + 4] = y2;
    out[i * 6 + 5] = s;
}

// ---------------- launch ----------------
extern "C" void kernel_launch(void* const* d_in, const int* in_sizes, int n_in,
                              void* d_out, int out_size) {
    const float* feats[5];
    for (int i = 0; i < 5; i++) feats[i] = (const float*)d_in[i];
    const float* im_info = (const float*)d_in[5];
    const float* convW = (const float*)d_in[6];
    const float* convB = (const float*)d_in[7];
    const float* sw = (const float*)d_in[8];
    const float* sb = (const float*)d_in[9];
    const float* bw = (const float*)d_in[10];
    const float* bb = (const float*)d_in[11];
    float* out = (float*)d_out;

    static cudaStream_t s2 = nullptr;
    static cudaEvent_t evFork = nullptr, evJoin = nullptr;
    if (!s2) {
        cudaStreamCreateWithFlags(&s2, cudaStreamNonBlocking);
        cudaEventCreateWithFlags(&evFork, cudaEventDisableTiming);
        cudaEventCreateWithFlags(&evJoin, cudaEventDisableTiming);
    }

    // fork: weight path (repackw -> fold) runs concurrent with prep (feature path)
    cudaEventRecord(evFork, 0);
    cudaStreamWaitEvent(s2, evFork, 0);
    repackw_kernel<<<(512 * 2304 + 255) / 256, 256, 0, s2>>>(convW);
    fold_kernel<<<(2304 * 3 + 255) / 256, 256, 0, s2>>>(sw, sb, convB);
    cudaEventRecord(evJoin, s2);
    prep_kernel<<<dim3(1109, 8), dim3(32, 32)>>>(feats[0], feats[1], feats[2],
                                                 feats[3], feats[4]);
    cudaStreamWaitEvent(0, evJoin, 0);

    approx_score_kernel<<<1109, 256>>>();
    select16_kernel<<<1, 1024>>>(POOL_K);
    mark_compact_kernel<<<416, 256>>>();
    exact_conv_kernel<<<dim3(256, 2), 256>>>(convB);
    heads_pool_kernel<<<128, 256>>>(sw, sb, bw, bb);
    compact_kernel<<<CAND_MAX / 256, 256>>>();
    rank_kernel<<<CAND_MAX / RB, RB>>>(im_info);
    iou_kernel<<<dim3(94, 94), 64>>>();
    nms_kernel<<<1, 32>>>();
    output_kernel<<<(POST_NMS + 255) / 256, 256>>>(out);
}